// round 1
// baseline (speedup 1.0000x reference)
#include <cuda_runtime.h>
#include <cuda_bf16.h>

// Problem constants
#define BB 4
#define SS 2048
#define DD 768
#define HH 12
#define DH 64
#define BH (BB*HH)          // 48
#define M_TOT (BB*SS)       // 8192

// Scratch: Q,K,V in [B,H,S,DH] layout
__device__ float g_q[BH * SS * DH];
__device__ float g_k[BH * SS * DH];
__device__ float g_v[BH * SS * DH];

// ---------------------------------------------------------------------------
// Kernel 1: fused QKV projection.  out[z] = X @ W[z] + b[z], written head-split.
// 128x128x8 tiling, 256 threads, 8x8 microtiles.
// grid = (M/128=64, N/128=6, 3)
// ---------------------------------------------------------------------------
__global__ __launch_bounds__(256, 2)
void qkv_kernel(const float* __restrict__ X,
                const float* __restrict__ Wq, const float* __restrict__ bq,
                const float* __restrict__ Wk, const float* __restrict__ bk,
                const float* __restrict__ Wv, const float* __restrict__ bv)
{
    __shared__ float As[8][128];   // A transposed: As[k][m]
    __shared__ float Bs[8][128];   // Bs[k][n]

    const int z = blockIdx.z;
    const float* W    = (z == 0) ? Wq : (z == 1) ? Wk : Wv;
    const float* bias = (z == 0) ? bq : (z == 1) ? bk : bv;
    float* out        = (z == 0) ? g_q : (z == 1) ? g_k : g_v;

    const int bm = blockIdx.x;     // 0..63
    const int bn = blockIdx.y;     // 0..5
    const int tid = threadIdx.x;
    const int tr = tid >> 4;       // 0..15
    const int tc = tid & 15;       // 0..15

    // load mapping
    const int aRow = tid >> 1;          // 0..127
    const int aCol = (tid & 1) * 4;     // 0 or 4
    const int bRow = tid >> 5;          // 0..7
    const int bCol = (tid & 31) * 4;    // 0..124

    const float* Aptr = X + (size_t)(bm * 128 + aRow) * DD + aCol;
    const float* Bptr = W + (size_t)bRow * DD + bn * 128 + bCol;

    float acc[8][8];
#pragma unroll
    for (int i = 0; i < 8; i++)
#pragma unroll
        for (int j = 0; j < 8; j++) acc[i][j] = 0.f;

    for (int k0 = 0; k0 < DD; k0 += 8) {
        float4 av = *(const float4*)(Aptr + k0);
        float4 bv4 = *(const float4*)(Bptr + (size_t)k0 * DD);

        As[aCol + 0][aRow] = av.x;
        As[aCol + 1][aRow] = av.y;
        As[aCol + 2][aRow] = av.z;
        As[aCol + 3][aRow] = av.w;
        *(float4*)&Bs[bRow][bCol] = bv4;
        __syncthreads();

#pragma unroll
        for (int k = 0; k < 8; k++) {
            float rm[8], rn[8];
#pragma unroll
            for (int i = 0; i < 8; i++) rm[i] = As[k][tr * 8 + i];
#pragma unroll
            for (int j = 0; j < 8; j++) rn[j] = Bs[k][tc * 8 + j];
#pragma unroll
            for (int i = 0; i < 8; i++)
#pragma unroll
                for (int j = 0; j < 8; j++)
                    acc[i][j] = fmaf(rm[i], rn[j], acc[i][j]);
        }
        __syncthreads();
    }

    // epilogue: add bias, store head-split [B,H,S,DH]
#pragma unroll
    for (int i = 0; i < 8; i++) {
        const int m = bm * 128 + tr * 8 + i;
        const int b = m >> 11;          // /2048
        const int s = m & 2047;
#pragma unroll
        for (int j = 0; j < 8; j++) {
            const int n = bn * 128 + tc * 8 + j;
            const int h = n >> 6;
            const int dh = n & 63;
            out[((size_t)(b * HH + h) * SS + s) * DH + dh] = acc[i][j] + __ldg(&bias[n]);
        }
    }
}

// ---------------------------------------------------------------------------
// Kernel 2: flash-style attention, fp32, online softmax.
// Tile: 64 queries x 64 keys, DH=64. 256 threads (16x16), 4x4 microtiles.
// grid = (S/64=32, B*H=48), dynamic smem = 4 * 64*68 floats = 69632 B
// ---------------------------------------------------------------------------
__device__ __forceinline__ float halfmax16(float v) {
    v = fmaxf(v, __shfl_xor_sync(0xffffffffu, v, 8));
    v = fmaxf(v, __shfl_xor_sync(0xffffffffu, v, 4));
    v = fmaxf(v, __shfl_xor_sync(0xffffffffu, v, 2));
    v = fmaxf(v, __shfl_xor_sync(0xffffffffu, v, 1));
    return v;
}
__device__ __forceinline__ float halfsum16(float v) {
    v += __shfl_xor_sync(0xffffffffu, v, 8);
    v += __shfl_xor_sync(0xffffffffu, v, 4);
    v += __shfl_xor_sync(0xffffffffu, v, 2);
    v += __shfl_xor_sync(0xffffffffu, v, 1);
    return v;
}

#define LDW 68  // padded row width (floats)

__global__ __launch_bounds__(256, 3)
void attn_kernel(const float* __restrict__ mask, float* __restrict__ out)
{
    extern __shared__ float sm[];
    float* Qs  = sm;                 // [64][68]
    float* KTs = sm + 64 * LDW;      // [64(k)][68(key)]  transposed K
    float* Vs  = sm + 2 * 64 * LDW;  // [64(key)][68(dh)]
    float* Ps  = sm + 3 * 64 * LDW;  // [64(q)][68(key)]

    const int tid = threadIdx.x;
    const int ty = tid >> 4;         // 0..15 -> query rows ty*4..+3
    const int tx = tid & 15;         // 0..15 -> cols tx*4..+3
    const int bh = blockIdx.y;
    const int b = bh / HH;
    const int h = bh % HH;
    const int q0 = blockIdx.x * 64;

    const float* Qg = g_q + (size_t)bh * SS * DH;
    const float* Kg = g_k + (size_t)bh * SS * DH;
    const float* Vg = g_v + (size_t)bh * SS * DH;
    const float* mrow = mask + (size_t)b * SS;

    // load Q tile, pre-scaled by 1/sqrt(DH) = 0.125
    for (int i = tid; i < 64 * 16; i += 256) {
        const int r = i >> 4, c4 = i & 15;
        float4 v = *(const float4*)(Qg + (size_t)(q0 + r) * DH + c4 * 4);
        v.x *= 0.125f; v.y *= 0.125f; v.z *= 0.125f; v.w *= 0.125f;
        *(float4*)(Qs + r * LDW + c4 * 4) = v;
    }

    float mrun[4], lrun[4], o[4][4];
#pragma unroll
    for (int i = 0; i < 4; i++) {
        mrun[i] = -1e30f; lrun[i] = 0.f;
#pragma unroll
        for (int j = 0; j < 4; j++) o[i][j] = 0.f;
    }

    for (int t = 0; t < SS / 64; t++) {
        const int k0 = t * 64;
        __syncthreads();   // prior-iter PV reads done; also publishes Qs at t=0

        // load K (transposed) and V tiles
        for (int i = tid; i < 64 * 16; i += 256) {
            const int j = i >> 4, c4 = i & 15;
            float4 kv = *(const float4*)(Kg + (size_t)(k0 + j) * DH + c4 * 4);
            KTs[(c4 * 4 + 0) * LDW + j] = kv.x;
            KTs[(c4 * 4 + 1) * LDW + j] = kv.y;
            KTs[(c4 * 4 + 2) * LDW + j] = kv.z;
            KTs[(c4 * 4 + 3) * LDW + j] = kv.w;
            float4 vv = *(const float4*)(Vg + (size_t)(k0 + j) * DH + c4 * 4);
            *(float4*)(Vs + j * LDW + c4 * 4) = vv;
        }
        __syncthreads();

        // scores: s[ii][jj] = sum_k Qs[qr][k] * KTs[k][kc]
        float s[4][4];
#pragma unroll
        for (int i = 0; i < 4; i++)
#pragma unroll
            for (int j = 0; j < 4; j++) s[i][j] = 0.f;

#pragma unroll 4
        for (int k = 0; k < 64; k++) {
            float a[4], kb[4];
#pragma unroll
            for (int i = 0; i < 4; i++) a[i] = Qs[(ty * 4 + i) * LDW + k];
#pragma unroll
            for (int j = 0; j < 4; j++) kb[j] = KTs[k * LDW + tx * 4 + j];
#pragma unroll
            for (int i = 0; i < 4; i++)
#pragma unroll
                for (int j = 0; j < 4; j++)
                    s[i][j] = fmaf(a[i], kb[j], s[i][j]);
        }

        // additive mask
        float mk[4];
#pragma unroll
        for (int j = 0; j < 4; j++) mk[j] = __ldg(mrow + k0 + tx * 4 + j);
#pragma unroll
        for (int i = 0; i < 4; i++)
#pragma unroll
            for (int j = 0; j < 4; j++) s[i][j] += mk[j];

        // online softmax (row stats replicated across the 16 tx lanes)
#pragma unroll
        for (int i = 0; i < 4; i++) {
            float rm = fmaxf(fmaxf(s[i][0], s[i][1]), fmaxf(s[i][2], s[i][3]));
            rm = halfmax16(rm);
            const float mn = fmaxf(mrun[i], rm);
            const float corr = __expf(mrun[i] - mn);
            float rs = 0.f;
#pragma unroll
            for (int j = 0; j < 4; j++) {
                const float p = __expf(s[i][j] - mn);
                Ps[(ty * 4 + i) * LDW + tx * 4 + j] = p;
                rs += p;
            }
            rs = halfsum16(rs);
            lrun[i] = lrun[i] * corr + rs;
#pragma unroll
            for (int j = 0; j < 4; j++) o[i][j] *= corr;
            mrun[i] = mn;
        }
        __syncthreads();

        // PV: o[ii][jj] += sum_k Ps[qr][k] * Vs[k][dh]
#pragma unroll 4
        for (int k = 0; k < 64; k++) {
            float p4[4], v4[4];
#pragma unroll
            for (int i = 0; i < 4; i++) p4[i] = Ps[(ty * 4 + i) * LDW + k];
#pragma unroll
            for (int j = 0; j < 4; j++) v4[j] = Vs[k * LDW + tx * 4 + j];
#pragma unroll
            for (int i = 0; i < 4; i++)
#pragma unroll
                for (int j = 0; j < 4; j++)
                    o[i][j] = fmaf(p4[i], v4[j], o[i][j]);
        }
    }

    // epilogue: normalize, write ctx in [B,S,D] layout
#pragma unroll
    for (int i = 0; i < 4; i++) {
        const float inv = 1.0f / lrun[i];
        const int srow = q0 + ty * 4 + i;
#pragma unroll
        for (int j = 0; j < 4; j++) {
            out[((size_t)(b * SS + srow)) * DD + h * DH + tx * 4 + j] = o[i][j] * inv;
        }
    }
}

// ---------------------------------------------------------------------------
extern "C" void kernel_launch(void* const* d_in, const int* in_sizes, int n_in,
                              void* d_out, int out_size)
{
    const float* hidden = (const float*)d_in[0];
    const float* mask   = (const float*)d_in[1];
    const float* Wq     = (const float*)d_in[2];
    const float* bq     = (const float*)d_in[3];
    const float* Wk     = (const float*)d_in[4];
    const float* bk     = (const float*)d_in[5];
    const float* Wv     = (const float*)d_in[6];
    const float* bv     = (const float*)d_in[7];
    float* out = (float*)d_out;

    const int smem_attn = 4 * 64 * LDW * sizeof(float);  // 69632 B
    cudaFuncSetAttribute(attn_kernel, cudaFuncAttributeMaxDynamicSharedMemorySize, smem_attn);

    qkv_kernel<<<dim3(64, 6, 3), 256>>>(hidden, Wq, bq, Wk, bk, Wv, bv);
    attn_kernel<<<dim3(SS / 64, BH), 256, smem_attn>>>(mask, out);
}

// round 2
// speedup vs baseline: 1.1334x; 1.1334x over previous
#include <cuda_runtime.h>
#include <cuda_bf16.h>

// Problem constants
#define BB 4
#define SS 2048
#define DD 768
#define HH 12
#define DH 64
#define BH (BB*HH)          // 48

// Scratch: Q,K,V in [B,H,S,DH] layout
__device__ float g_q[BH * SS * DH];
__device__ float g_k[BH * SS * DH];
__device__ float g_v[BH * SS * DH];

// ---------------------------------------------------------------------------
// Kernel 1: fused QKV projection (unchanged from R1 — already fma-bound).
// ---------------------------------------------------------------------------
__global__ __launch_bounds__(256, 2)
void qkv_kernel(const float* __restrict__ X,
                const float* __restrict__ Wq, const float* __restrict__ bq,
                const float* __restrict__ Wk, const float* __restrict__ bk,
                const float* __restrict__ Wv, const float* __restrict__ bv)
{
    __shared__ float As[8][128];   // A transposed: As[k][m]
    __shared__ float Bs[8][128];   // Bs[k][n]

    const int z = blockIdx.z;
    const float* W    = (z == 0) ? Wq : (z == 1) ? Wk : Wv;
    const float* bias = (z == 0) ? bq : (z == 1) ? bk : bv;
    float* out        = (z == 0) ? g_q : (z == 1) ? g_k : g_v;

    const int bm = blockIdx.x;
    const int bn = blockIdx.y;
    const int tid = threadIdx.x;
    const int tr = tid >> 4;
    const int tc = tid & 15;

    const int aRow = tid >> 1;
    const int aCol = (tid & 1) * 4;
    const int bRow = tid >> 5;
    const int bCol = (tid & 31) * 4;

    const float* Aptr = X + (size_t)(bm * 128 + aRow) * DD + aCol;
    const float* Bptr = W + (size_t)bRow * DD + bn * 128 + bCol;

    float acc[8][8];
#pragma unroll
    for (int i = 0; i < 8; i++)
#pragma unroll
        for (int j = 0; j < 8; j++) acc[i][j] = 0.f;

    for (int k0 = 0; k0 < DD; k0 += 8) {
        float4 av = *(const float4*)(Aptr + k0);
        float4 bv4 = *(const float4*)(Bptr + (size_t)k0 * DD);

        As[aCol + 0][aRow] = av.x;
        As[aCol + 1][aRow] = av.y;
        As[aCol + 2][aRow] = av.z;
        As[aCol + 3][aRow] = av.w;
        *(float4*)&Bs[bRow][bCol] = bv4;
        __syncthreads();

#pragma unroll
        for (int k = 0; k < 8; k++) {
            float rm[8], rn[8];
#pragma unroll
            for (int i = 0; i < 8; i++) rm[i] = As[k][tr * 8 + i];
#pragma unroll
            for (int j = 0; j < 8; j++) rn[j] = Bs[k][tc * 8 + j];
#pragma unroll
            for (int i = 0; i < 8; i++)
#pragma unroll
                for (int j = 0; j < 8; j++)
                    acc[i][j] = fmaf(rm[i], rn[j], acc[i][j]);
        }
        __syncthreads();
    }

#pragma unroll
    for (int i = 0; i < 8; i++) {
        const int m = bm * 128 + tr * 8 + i;
        const int b = m >> 11;
        const int s = m & 2047;
#pragma unroll
        for (int j = 0; j < 8; j++) {
            const int n = bn * 128 + tc * 8 + j;
            const int h = n >> 6;
            const int dh = n & 63;
            out[((size_t)(b * HH + h) * SS + s) * DH + dh] = acc[i][j] + __ldg(&bias[n]);
        }
    }
}

// ---------------------------------------------------------------------------
// Kernel 2: flash attention, fp32, 128q x 64k tile, 8x4 microtile, float4 LDS.
// 256 threads (16x16). 2 CTAs/SM (101.25 KB dyn smem each).
// grid = (S/128 = 16, B*H = 48)
// ---------------------------------------------------------------------------
__device__ __forceinline__ float halfmax16(float v) {
    v = fmaxf(v, __shfl_xor_sync(0xffffffffu, v, 8));
    v = fmaxf(v, __shfl_xor_sync(0xffffffffu, v, 4));
    v = fmaxf(v, __shfl_xor_sync(0xffffffffu, v, 2));
    v = fmaxf(v, __shfl_xor_sync(0xffffffffu, v, 1));
    return v;
}
__device__ __forceinline__ float halfsum16(float v) {
    v += __shfl_xor_sync(0xffffffffu, v, 8);
    v += __shfl_xor_sync(0xffffffffu, v, 4);
    v += __shfl_xor_sync(0xffffffffu, v, 2);
    v += __shfl_xor_sync(0xffffffffu, v, 1);
    return v;
}

#define QRW 132   // Qs row width: [64 dh][128 q + pad]
#define KRW 68    // KTs/Vs/Ps row width

// smem floats: Qs 64*132 + KTs 64*68 + Vs 64*68 + Ps 128*68 + mask 64
#define SM_FLOATS (64*QRW + 64*KRW + 64*KRW + 128*KRW + 64)

__global__ __launch_bounds__(256, 2)
void attn_kernel(const float* __restrict__ mask, float* __restrict__ out)
{
    extern __shared__ float sm[];
    float* Qs  = sm;                       // [64][132]  Qs[d][q], pre-scaled
    float* KTs = Qs + 64 * QRW;            // [64][68]   KTs[d][key]
    float* Vs  = KTs + 64 * KRW;           // [64][68]   Vs[key][dh]
    float* Ps  = Vs + 64 * KRW;            // [128][68]  Ps[q][key]
    float* Ms  = Ps + 128 * KRW;           // [64] mask tile

    const int tid = threadIdx.x;
    const int ty = tid >> 4;               // 0..15 -> q rows ty*8..+7
    const int tx = tid & 15;               // 0..15 -> 4-wide cols tx*4..+3
    const int bh = blockIdx.y;
    const int b = bh / HH;
    const int h = bh % HH;
    const int q0 = blockIdx.x * 128;

    const float* Qg = g_q + (size_t)bh * SS * DH;
    const float* Kg = g_k + (size_t)bh * SS * DH;
    const float* Vg = g_v + (size_t)bh * SS * DH;
    const float* mrow = mask + (size_t)b * SS;

    // ---- load Q tile transposed (4x4 register-block transpose), scaled 0.125
#pragma unroll
    for (int it = 0; it < 2; it++) {
        const int blk = it * 256 + tid;
        const int db = blk & 15;           // dh block 0..15
        const int qb = blk >> 4;           // q block 0..31
        const float* src = Qg + (size_t)(q0 + qb * 4) * DH + db * 4;
        float4 x0 = *(const float4*)(src);
        float4 x1 = *(const float4*)(src + DH);
        float4 x2 = *(const float4*)(src + 2 * DH);
        float4 x3 = *(const float4*)(src + 3 * DH);
        float* dst = Qs + (db * 4) * QRW + qb * 4;
        *(float4*)(dst + 0 * QRW) = make_float4(x0.x*0.125f, x1.x*0.125f, x2.x*0.125f, x3.x*0.125f);
        *(float4*)(dst + 1 * QRW) = make_float4(x0.y*0.125f, x1.y*0.125f, x2.y*0.125f, x3.y*0.125f);
        *(float4*)(dst + 2 * QRW) = make_float4(x0.z*0.125f, x1.z*0.125f, x2.z*0.125f, x3.z*0.125f);
        *(float4*)(dst + 3 * QRW) = make_float4(x0.w*0.125f, x1.w*0.125f, x2.w*0.125f, x3.w*0.125f);
    }

    float mrun[8], lrun[8], o[8][4];
#pragma unroll
    for (int i = 0; i < 8; i++) {
        mrun[i] = -1e30f; lrun[i] = 0.f;
#pragma unroll
        for (int j = 0; j < 4; j++) o[i][j] = 0.f;
    }

    for (int t = 0; t < SS / 64; t++) {
        const int k0 = t * 64;
        __syncthreads();   // prev-iter PV reads of KTs/Vs/Ps done (covers Qs at t=0)

        // ---- load K tile transposed (4x4 block transpose): 64 keys x 64 dh
        {
            const int db = tid & 15;       // dh block 0..15
            const int kb = tid >> 4;       // key block 0..15
            const float* src = Kg + (size_t)(k0 + kb * 4) * DH + db * 4;
            float4 x0 = *(const float4*)(src);
            float4 x1 = *(const float4*)(src + DH);
            float4 x2 = *(const float4*)(src + 2 * DH);
            float4 x3 = *(const float4*)(src + 3 * DH);
            float* dst = KTs + (db * 4) * KRW + kb * 4;
            *(float4*)(dst + 0 * KRW) = make_float4(x0.x, x1.x, x2.x, x3.x);
            *(float4*)(dst + 1 * KRW) = make_float4(x0.y, x1.y, x2.y, x3.y);
            *(float4*)(dst + 2 * KRW) = make_float4(x0.z, x1.z, x2.z, x3.z);
            *(float4*)(dst + 3 * KRW) = make_float4(x0.w, x1.w, x2.w, x3.w);
        }
        // ---- load V tile straight: 64 keys x 64 dh
#pragma unroll
        for (int it = 0; it < 4; it++) {
            const int i = it * 256 + tid;
            const int r = i >> 4, c4 = i & 15;
            *(float4*)(Vs + r * KRW + c4 * 4) =
                *(const float4*)(Vg + (size_t)(k0 + r) * DH + c4 * 4);
        }
        // ---- mask tile
        if (tid < 64) Ms[tid] = __ldg(mrow + k0 + tid);
        __syncthreads();

        // ---- QK: s[i][j] = sum_d Qs[d][ty*8+i] * KTs[d][tx*4+j]
        float s[8][4];
#pragma unroll
        for (int i = 0; i < 8; i++)
#pragma unroll
            for (int j = 0; j < 4; j++) s[i][j] = 0.f;

#pragma unroll 4
        for (int d = 0; d < 64; d++) {
            float4 qa = *(const float4*)(Qs + d * QRW + ty * 8);
            float4 qb4 = *(const float4*)(Qs + d * QRW + ty * 8 + 4);
            float4 kv = *(const float4*)(KTs + d * KRW + tx * 4);
            float rm[8];
            rm[0] = qa.x; rm[1] = qa.y; rm[2] = qa.z; rm[3] = qa.w;
            rm[4] = qb4.x; rm[5] = qb4.y; rm[6] = qb4.z; rm[7] = qb4.w;
#pragma unroll
            for (int i = 0; i < 8; i++) {
                s[i][0] = fmaf(rm[i], kv.x, s[i][0]);
                s[i][1] = fmaf(rm[i], kv.y, s[i][1]);
                s[i][2] = fmaf(rm[i], kv.z, s[i][2]);
                s[i][3] = fmaf(rm[i], kv.w, s[i][3]);
            }
        }

        // ---- mask + online softmax, write P tile
        float mk[4];
#pragma unroll
        for (int j = 0; j < 4; j++) mk[j] = Ms[tx * 4 + j];

#pragma unroll
        for (int i = 0; i < 8; i++) {
#pragma unroll
            for (int j = 0; j < 4; j++) s[i][j] += mk[j];
            float rmx = fmaxf(fmaxf(s[i][0], s[i][1]), fmaxf(s[i][2], s[i][3]));
            rmx = halfmax16(rmx);
            const float mn = fmaxf(mrun[i], rmx);
            const float corr = __expf(mrun[i] - mn);
            float rs = 0.f;
#pragma unroll
            for (int j = 0; j < 4; j++) {
                const float p = __expf(s[i][j] - mn);
                s[i][j] = p;
                rs += p;
            }
            rs = halfsum16(rs);
            lrun[i] = lrun[i] * corr + rs;
#pragma unroll
            for (int j = 0; j < 4; j++) o[i][j] *= corr;
            mrun[i] = mn;
            *(float4*)(Ps + (ty * 8 + i) * KRW + tx * 4) =
                make_float4(s[i][0], s[i][1], s[i][2], s[i][3]);
        }
        __syncthreads();

        // ---- PV: o[i][j] += sum_k Ps[q][k] * Vs[k][dh], key-unrolled x4
#pragma unroll 2
        for (int k = 0; k < 64; k += 4) {
            float4 pf[8];
#pragma unroll
            for (int i = 0; i < 8; i++)
                pf[i] = *(const float4*)(Ps + (ty * 8 + i) * KRW + k);
            float4 v0 = *(const float4*)(Vs + (k + 0) * KRW + tx * 4);
            float4 v1 = *(const float4*)(Vs + (k + 1) * KRW + tx * 4);
            float4 v2 = *(const float4*)(Vs + (k + 2) * KRW + tx * 4);
            float4 v3 = *(const float4*)(Vs + (k + 3) * KRW + tx * 4);
#pragma unroll
            for (int i = 0; i < 8; i++) {
                o[i][0] = fmaf(pf[i].x, v0.x, o[i][0]);
                o[i][1] = fmaf(pf[i].x, v0.y, o[i][1]);
                o[i][2] = fmaf(pf[i].x, v0.z, o[i][2]);
                o[i][3] = fmaf(pf[i].x, v0.w, o[i][3]);
                o[i][0] = fmaf(pf[i].y, v1.x, o[i][0]);
                o[i][1] = fmaf(pf[i].y, v1.y, o[i][1]);
                o[i][2] = fmaf(pf[i].y, v1.z, o[i][2]);
                o[i][3] = fmaf(pf[i].y, v1.w, o[i][3]);
                o[i][0] = fmaf(pf[i].z, v2.x, o[i][0]);
                o[i][1] = fmaf(pf[i].z, v2.y, o[i][1]);
                o[i][2] = fmaf(pf[i].z, v2.z, o[i][2]);
                o[i][3] = fmaf(pf[i].z, v2.w, o[i][3]);
                o[i][0] = fmaf(pf[i].w, v3.x, o[i][0]);
                o[i][1] = fmaf(pf[i].w, v3.y, o[i][1]);
                o[i][2] = fmaf(pf[i].w, v3.z, o[i][2]);
                o[i][3] = fmaf(pf[i].w, v3.w, o[i][3]);
            }
        }
    }

    // ---- epilogue: normalize, write ctx [B,S,D]
#pragma unroll
    for (int i = 0; i < 8; i++) {
        const float inv = 1.0f / lrun[i];
        const int srow = q0 + ty * 8 + i;
        *(float4*)(out + (size_t)(b * SS + srow) * DD + h * DH + tx * 4) =
            make_float4(o[i][0] * inv, o[i][1] * inv, o[i][2] * inv, o[i][3] * inv);
    }
}

// ---------------------------------------------------------------------------
extern "C" void kernel_launch(void* const* d_in, const int* in_sizes, int n_in,
                              void* d_out, int out_size)
{
    const float* hidden = (const float*)d_in[0];
    const float* mask   = (const float*)d_in[1];
    const float* Wq     = (const float*)d_in[2];
    const float* bq     = (const float*)d_in[3];
    const float* Wk     = (const float*)d_in[4];
    const float* bk     = (const float*)d_in[5];
    const float* Wv     = (const float*)d_in[6];
    const float* bv     = (const float*)d_in[7];
    float* out = (float*)d_out;

    const int smem_attn = SM_FLOATS * sizeof(float);  // 103680 B
    cudaFuncSetAttribute(attn_kernel, cudaFuncAttributeMaxDynamicSharedMemorySize, smem_attn);

    qkv_kernel<<<dim3(64, 6, 3), 256>>>(hidden, Wq, bq, Wk, bk, Wv, bv);
    attn_kernel<<<dim3(SS / 128, BH), 256, smem_attn>>>(mask, out);
}

// round 4
// speedup vs baseline: 1.8810x; 1.6596x over previous
#include <cuda_runtime.h>
#include <cuda_bf16.h>
#include <cstdint>

// Problem constants
#define BB 4
#define SS 2048
#define DD 768
#define HH 12
#define DH 64
#define BH (BB*HH)          // 48

// Scratch: Q,K,V in [B,H,S,DH] layout
__device__ float g_q[BH * SS * DH];
__device__ float g_k[BH * SS * DH];
__device__ float g_v[BH * SS * DH];

// ---------------------------------------------------------------------------
// Kernel 1: fused QKV projection (FFMA, unchanged — control for rel_err).
// ---------------------------------------------------------------------------
__global__ __launch_bounds__(256, 2)
void qkv_kernel(const float* __restrict__ X,
                const float* __restrict__ Wq, const float* __restrict__ bq,
                const float* __restrict__ Wk, const float* __restrict__ bk,
                const float* __restrict__ Wv, const float* __restrict__ bv)
{
    __shared__ float As[8][128];
    __shared__ float Bs[8][128];

    const int z = blockIdx.z;
    const float* W    = (z == 0) ? Wq : (z == 1) ? Wk : Wv;
    const float* bias = (z == 0) ? bq : (z == 1) ? bk : bv;
    float* out        = (z == 0) ? g_q : (z == 1) ? g_k : g_v;

    const int bm = blockIdx.x;
    const int bn = blockIdx.y;
    const int tid = threadIdx.x;
    const int tr = tid >> 4;
    const int tc = tid & 15;

    const int aRow = tid >> 1;
    const int aCol = (tid & 1) * 4;
    const int bRow = tid >> 5;
    const int bCol = (tid & 31) * 4;

    const float* Aptr = X + (size_t)(bm * 128 + aRow) * DD + aCol;
    const float* Bptr = W + (size_t)bRow * DD + bn * 128 + bCol;

    float acc[8][8];
#pragma unroll
    for (int i = 0; i < 8; i++)
#pragma unroll
        for (int j = 0; j < 8; j++) acc[i][j] = 0.f;

    for (int k0 = 0; k0 < DD; k0 += 8) {
        float4 av = *(const float4*)(Aptr + k0);
        float4 bv4 = *(const float4*)(Bptr + (size_t)k0 * DD);

        As[aCol + 0][aRow] = av.x;
        As[aCol + 1][aRow] = av.y;
        As[aCol + 2][aRow] = av.z;
        As[aCol + 3][aRow] = av.w;
        *(float4*)&Bs[bRow][bCol] = bv4;
        __syncthreads();

#pragma unroll
        for (int k = 0; k < 8; k++) {
            float rm[8], rn[8];
#pragma unroll
            for (int i = 0; i < 8; i++) rm[i] = As[k][tr * 8 + i];
#pragma unroll
            for (int j = 0; j < 8; j++) rn[j] = Bs[k][tc * 8 + j];
#pragma unroll
            for (int i = 0; i < 8; i++)
#pragma unroll
                for (int j = 0; j < 8; j++)
                    acc[i][j] = fmaf(rm[i], rn[j], acc[i][j]);
        }
        __syncthreads();
    }

#pragma unroll
    for (int i = 0; i < 8; i++) {
        const int m = bm * 128 + tr * 8 + i;
        const int b = m >> 11;
        const int s = m & 2047;
#pragma unroll
        for (int j = 0; j < 8; j++) {
            const int n = bn * 128 + tc * 8 + j;
            const int h = n >> 6;
            const int dh = n & 63;
            out[((size_t)(b * HH + h) * SS + s) * DH + dh] = acc[i][j] + __ldg(&bias[n]);
        }
    }
}

// ---------------------------------------------------------------------------
// Tensor-core helpers (mma.sync m16n8k8 tf32 + ldmatrix)
// ---------------------------------------------------------------------------
__device__ __forceinline__ float tf32r(float x) {
    uint32_t u;
    asm("cvt.rna.tf32.f32 %0, %1;" : "=r"(u) : "f"(x));
    return __uint_as_float(u);
}
__device__ __forceinline__ void ldsm_x4(uint32_t& r0, uint32_t& r1, uint32_t& r2, uint32_t& r3, uint32_t a) {
    asm volatile("ldmatrix.sync.aligned.m8n8.x4.shared.b16 {%0,%1,%2,%3}, [%4];"
                 : "=r"(r0), "=r"(r1), "=r"(r2), "=r"(r3) : "r"(a));
}
__device__ __forceinline__ void ldsm_x2(uint32_t& r0, uint32_t& r1, uint32_t a) {
    asm volatile("ldmatrix.sync.aligned.m8n8.x2.shared.b16 {%0,%1}, [%2];"
                 : "=r"(r0), "=r"(r1) : "r"(a));
}
__device__ __forceinline__ void mma_tf32(float (&d)[4],
                                         uint32_t a0, uint32_t a1, uint32_t a2, uint32_t a3,
                                         uint32_t b0, uint32_t b1) {
    asm volatile("mma.sync.aligned.m16n8k8.row.col.f32.tf32.tf32.f32 "
                 "{%0,%1,%2,%3}, {%4,%5,%6,%7}, {%8,%9}, {%0,%1,%2,%3};"
                 : "+f"(d[0]), "+f"(d[1]), "+f"(d[2]), "+f"(d[3])
                 : "r"(a0), "r"(a1), "r"(a2), "r"(a3), "r"(b0), "r"(b1));
}

// ---------------------------------------------------------------------------
// Kernel 2: flash attention on tensor cores (tf32 mma.sync).
// 128q tile x 64-key steps. 256 threads / 8 warps; warp w owns q rows
// [w*16, w*16+16) x all 64 keys -> softmax fully warp-local.
// grid = (S/128 = 16, B*H = 48)
// ---------------------------------------------------------------------------
#define RW 68   // smem row stride (floats): conflict-free for ldmatrix

// Qs 128*RW + Ks 64*RW + VTs 64*RW + Ps 128*RW + Ms 64
#define SMF (128*RW + 64*RW + 64*RW + 128*RW + 64)

__global__ __launch_bounds__(256, 2)
void attn_kernel(const float* __restrict__ mask, float* __restrict__ out)
{
    extern __shared__ float sm[];
    float* Qs  = sm;                 // [128][RW] Q (prescaled 0.125, tf32)
    float* Ks  = Qs + 128 * RW;      // [64][RW]  K rows [key][dh] (tf32)
    float* VTs = Ks + 64 * RW;       // [64][RW]  V transposed [dh][key] (tf32)
    float* Ps  = VTs + 64 * RW;      // [128][RW] P tile (tf32)
    float* Ms  = Ps + 128 * RW;      // [64] mask

    const int tid = threadIdx.x;
    const int w = tid >> 5;          // warp 0..7
    const int l = tid & 31;          // lane
    const int tg = l & 3;            // threadID_in_group
    const int grp = l >> 2;          // groupID (row within m16)

    const int bh = blockIdx.y;
    const int b = bh / HH;
    const int h = bh % HH;
    const int q0 = blockIdx.x * 128;

    const float* Qg = g_q + (size_t)bh * SS * DH;
    const float* Kg = g_k + (size_t)bh * SS * DH;
    const float* Vg = g_v + (size_t)bh * SS * DH;
    const float* mrow = mask + (size_t)b * SS;

    const uint32_t qs_u  = (uint32_t)__cvta_generic_to_shared(Qs);
    const uint32_t ks_u  = (uint32_t)__cvta_generic_to_shared(Ks);
    const uint32_t vts_u = (uint32_t)__cvta_generic_to_shared(VTs);
    const uint32_t ps_u  = (uint32_t)__cvta_generic_to_shared(Ps);

    // A-fragment ldmatrix lane addressing: row = l&15, +4 cols if l>=16
    const int aRow = w * 16 + (l & 15);
    const int aColX = (l >> 4) * 4;
    const uint32_t aQ = qs_u + (uint32_t)(aRow * RW + aColX) * 4u;
    const uint32_t aP = ps_u + (uint32_t)(aRow * RW + aColX) * 4u;
    // B-fragment ldmatrix lane addressing (x2): row = l&7 (+n*8), col = ((l>>3)&1)*4
    const int bRow = (l & 7);
    const int bColX = ((l >> 3) & 1) * 4;
    const uint32_t bK = ks_u  + (uint32_t)(bRow * RW + bColX) * 4u;
    const uint32_t bV = vts_u + (uint32_t)(bRow * RW + bColX) * 4u;

    // ---- load Q tile (prescale 0.125, round to tf32)
    for (int i = tid; i < 128 * 16; i += 256) {
        const int r = i >> 4, c4 = i & 15;
        float4 v = *(const float4*)(Qg + (size_t)(q0 + r) * DH + c4 * 4);
        float4 o4 = make_float4(tf32r(v.x * 0.125f), tf32r(v.y * 0.125f),
                                tf32r(v.z * 0.125f), tf32r(v.w * 0.125f));
        *(float4*)(Qs + r * RW + c4 * 4) = o4;
    }

    float o[8][4];
#pragma unroll
    for (int n = 0; n < 8; n++)
#pragma unroll
        for (int j = 0; j < 4; j++) o[n][j] = 0.f;
    float mr0 = -1e30f, mr1 = -1e30f, lr0 = 0.f, lr1 = 0.f;

    for (int t = 0; t < SS / 64; t++) {
        const int k0 = t * 64;
        __syncthreads();   // prior iter QK(Ks)/PV(VTs) reads done; covers Qs at t=0

        // ---- load K tile [key][dh], tf32
#pragma unroll
        for (int it = 0; it < 4; it++) {
            const int i = it * 256 + tid;
            const int r = i >> 4, c4 = i & 15;
            float4 v = *(const float4*)(Kg + (size_t)(k0 + r) * DH + c4 * 4);
            *(float4*)(Ks + r * RW + c4 * 4) =
                make_float4(tf32r(v.x), tf32r(v.y), tf32r(v.z), tf32r(v.w));
        }
        // ---- load V transposed [dh][key] via 4x4 block transpose, tf32
        {
            const int db = tid & 15;      // dh block
            const int kb = tid >> 4;      // key block
            const float* src = Vg + (size_t)(k0 + kb * 4) * DH + db * 4;
            float4 x0 = *(const float4*)(src);
            float4 x1 = *(const float4*)(src + DH);
            float4 x2 = *(const float4*)(src + 2 * DH);
            float4 x3 = *(const float4*)(src + 3 * DH);
            float* dst = VTs + (db * 4) * RW + kb * 4;
            *(float4*)(dst + 0 * RW) = make_float4(tf32r(x0.x), tf32r(x1.x), tf32r(x2.x), tf32r(x3.x));
            *(float4*)(dst + 1 * RW) = make_float4(tf32r(x0.y), tf32r(x1.y), tf32r(x2.y), tf32r(x3.y));
            *(float4*)(dst + 2 * RW) = make_float4(tf32r(x0.z), tf32r(x1.z), tf32r(x2.z), tf32r(x3.z));
            *(float4*)(dst + 3 * RW) = make_float4(tf32r(x0.w), tf32r(x1.w), tf32r(x2.w), tf32r(x3.w));
        }
        if (tid < 64) Ms[tid] = __ldg(mrow + k0 + tid);
        __syncthreads();

        // ---- QK: S(16x64) = Q(16xDH) * K^T, 8 k-steps x 8 n-tiles
        float s[8][4];
#pragma unroll
        for (int n = 0; n < 8; n++)
#pragma unroll
            for (int j = 0; j < 4; j++) s[n][j] = 0.f;

#pragma unroll
        for (int kk = 0; kk < 8; kk++) {
            uint32_t a0, a1, a2, a3;
            ldsm_x4(a0, a1, a2, a3, aQ + kk * 32u);
#pragma unroll
            for (int n = 0; n < 8; n++) {
                uint32_t b0, b1;
                ldsm_x2(b0, b1, bK + (uint32_t)(n * 8 * RW) * 4u + kk * 32u);
                mma_tf32(s[n], a0, a1, a2, a3, b0, b1);
            }
        }

        // ---- mask + online softmax (rows grp, grp+8 of this warp's block)
        float rx0 = -1e30f, rx1 = -1e30f;
#pragma unroll
        for (int n = 0; n < 8; n++) {
            const float mk0 = Ms[n * 8 + 2 * tg];
            const float mk1 = Ms[n * 8 + 2 * tg + 1];
            s[n][0] += mk0; s[n][1] += mk1;
            s[n][2] += mk0; s[n][3] += mk1;
            rx0 = fmaxf(rx0, fmaxf(s[n][0], s[n][1]));
            rx1 = fmaxf(rx1, fmaxf(s[n][2], s[n][3]));
        }
        rx0 = fmaxf(rx0, __shfl_xor_sync(0xffffffffu, rx0, 1));
        rx0 = fmaxf(rx0, __shfl_xor_sync(0xffffffffu, rx0, 2));
        rx1 = fmaxf(rx1, __shfl_xor_sync(0xffffffffu, rx1, 1));
        rx1 = fmaxf(rx1, __shfl_xor_sync(0xffffffffu, rx1, 2));

        const float mn0 = fmaxf(mr0, rx0);
        const float mn1 = fmaxf(mr1, rx1);
        const float c0 = __expf(mr0 - mn0);
        const float c1 = __expf(mr1 - mn1);

        const int row0 = w * 16 + grp;
        const int row1 = row0 + 8;
        float sum0 = 0.f, sum1 = 0.f;
#pragma unroll
        for (int n = 0; n < 8; n++) {
            const float p00 = __expf(s[n][0] - mn0);
            const float p01 = __expf(s[n][1] - mn0);
            const float p10 = __expf(s[n][2] - mn1);
            const float p11 = __expf(s[n][3] - mn1);
            sum0 += p00 + p01;
            sum1 += p10 + p11;
            *(float2*)(Ps + row0 * RW + n * 8 + 2 * tg) = make_float2(tf32r(p00), tf32r(p01));
            *(float2*)(Ps + row1 * RW + n * 8 + 2 * tg) = make_float2(tf32r(p10), tf32r(p11));
        }
        sum0 += __shfl_xor_sync(0xffffffffu, sum0, 1);
        sum0 += __shfl_xor_sync(0xffffffffu, sum0, 2);
        sum1 += __shfl_xor_sync(0xffffffffu, sum1, 1);
        sum1 += __shfl_xor_sync(0xffffffffu, sum1, 2);

        lr0 = lr0 * c0 + sum0;
        lr1 = lr1 * c1 + sum1;
        mr0 = mn0; mr1 = mn1;
#pragma unroll
        for (int n = 0; n < 8; n++) {
            o[n][0] *= c0; o[n][1] *= c0;
            o[n][2] *= c1; o[n][3] *= c1;
        }
        __syncwarp();   // Ps is warp-private: publish stores to ldmatrix lanes

        // ---- PV: O(16x64) += P(16x64) * V, 8 key-steps x 8 dh-tiles
#pragma unroll
        for (int kk = 0; kk < 8; kk++) {
            uint32_t a0, a1, a2, a3;
            ldsm_x4(a0, a1, a2, a3, aP + kk * 32u);
#pragma unroll
            for (int n = 0; n < 8; n++) {
                uint32_t b0, b1;
                ldsm_x2(b0, b1, bV + (uint32_t)(n * 8 * RW) * 4u + kk * 32u);
                mma_tf32(o[n], a0, a1, a2, a3, b0, b1);
            }
        }
    }

    // ---- epilogue: normalize, write ctx [B,S,D]
    const float inv0 = 1.0f / lr0;
    const float inv1 = 1.0f / lr1;
    const int r0 = q0 + w * 16 + grp;
    const int r1 = r0 + 8;
#pragma unroll
    for (int n = 0; n < 8; n++) {
        const int col = h * DH + n * 8 + 2 * tg;
        *(float2*)(out + (size_t)(b * SS + r0) * DD + col) =
            make_float2(o[n][0] * inv0, o[n][1] * inv0);
        *(float2*)(out + (size_t)(b * SS + r1) * DD + col) =
            make_float2(o[n][2] * inv1, o[n][3] * inv1);
    }
}

// ---------------------------------------------------------------------------
extern "C" void kernel_launch(void* const* d_in, const int* in_sizes, int n_in,
                              void* d_out, int out_size)
{
    const float* hidden = (const float*)d_in[0];
    const float* mask   = (const float*)d_in[1];
    const float* Wq     = (const float*)d_in[2];
    const float* bq     = (const float*)d_in[3];
    const float* Wk     = (const float*)d_in[4];
    const float* bk     = (const float*)d_in[5];
    const float* Wv     = (const float*)d_in[6];
    const float* bv     = (const float*)d_in[7];
    float* out = (float*)d_out;

    const int smem_attn = SMF * sizeof(float);   // 104704 B
    cudaFuncSetAttribute(attn_kernel, cudaFuncAttributeMaxDynamicSharedMemorySize, smem_attn);

    qkv_kernel<<<dim3(64, 6, 3), 256>>>(hidden, Wq, bq, Wk, bk, Wv, bv);
    attn_kernel<<<dim3(SS / 128, BH), 256, smem_attn>>>(mask, out);
}

// round 5
// speedup vs baseline: 2.8777x; 1.5299x over previous
#include <cuda_runtime.h>
#include <cuda_bf16.h>
#include <cstdint>

// Problem constants
#define BB 4
#define SS 2048
#define DD 768
#define HH 12
#define DH 64
#define BH (BB*HH)          // 48

// Scratch: Q,K,V in [B,H,S,DH] layout
__device__ float g_q[BH * SS * DH];
__device__ float g_k[BH * SS * DH];
__device__ float g_v[BH * SS * DH];

// ---------------------------------------------------------------------------
// Tensor-core helpers (mma.sync m16n8k8 tf32 + ldmatrix)
// ---------------------------------------------------------------------------
__device__ __forceinline__ float tf32r(float x) {
    uint32_t u;
    asm("cvt.rna.tf32.f32 %0, %1;" : "=r"(u) : "f"(x));
    return __uint_as_float(u);
}
__device__ __forceinline__ void ldsm_x4(uint32_t& r0, uint32_t& r1, uint32_t& r2, uint32_t& r3, uint32_t a) {
    asm volatile("ldmatrix.sync.aligned.m8n8.x4.shared.b16 {%0,%1,%2,%3}, [%4];"
                 : "=r"(r0), "=r"(r1), "=r"(r2), "=r"(r3) : "r"(a));
}
__device__ __forceinline__ void ldsm_x2(uint32_t& r0, uint32_t& r1, uint32_t a) {
    asm volatile("ldmatrix.sync.aligned.m8n8.x2.shared.b16 {%0,%1}, [%2];"
                 : "=r"(r0), "=r"(r1) : "r"(a));
}
__device__ __forceinline__ void mma_tf32(float (&d)[4],
                                         uint32_t a0, uint32_t a1, uint32_t a2, uint32_t a3,
                                         uint32_t b0, uint32_t b1) {
    asm volatile("mma.sync.aligned.m16n8k8.row.col.f32.tf32.tf32.f32 "
                 "{%0,%1,%2,%3}, {%4,%5,%6,%7}, {%8,%9}, {%0,%1,%2,%3};"
                 : "+f"(d[0]), "+f"(d[1]), "+f"(d[2]), "+f"(d[3])
                 : "r"(a0), "r"(a1), "r"(a2), "r"(a3), "r"(b0), "r"(b1));
}

// ---------------------------------------------------------------------------
// Kernel 1: fused QKV projection on tensor cores (tf32 mma.sync).
// CTA tile 128m x 128n, K-step 16. 8 warps in 4x2: warp tile m32 x n64.
// grid = (64, 6, 3)
// ---------------------------------------------------------------------------
#define XRW 20   // Xs/Ws row stride in floats (16 k + 4 pad) -> conflict-free ldmatrix

__global__ __launch_bounds__(256, 2)
void qkv_kernel(const float* __restrict__ X,
                const float* __restrict__ Wq, const float* __restrict__ bq,
                const float* __restrict__ Wk, const float* __restrict__ bk,
                const float* __restrict__ Wv, const float* __restrict__ bv)
{
    __shared__ float Xs[128 * XRW];   // [m][k] rows
    __shared__ float Ws[128 * XRW];   // [n][k] rows (W transposed)

    const int z = blockIdx.z;
    const float* W    = (z == 0) ? Wq : (z == 1) ? Wk : Wv;
    const float* bias = (z == 0) ? bq : (z == 1) ? bk : bv;
    float* out        = (z == 0) ? g_q : (z == 1) ? g_k : g_v;

    const int bm = blockIdx.x;          // m block (128 rows)
    const int bn = blockIdx.y;          // n block (128 cols)
    const int tid = threadIdx.x;
    const int w = tid >> 5;
    const int l = tid & 31;
    const int tg = l & 3;
    const int grp = l >> 2;

    const int warpM = (w >> 1) * 32;    // 0,32,64,96
    const int warpN = (w & 1) * 64;     // 0,64

    const uint32_t xs_u = (uint32_t)__cvta_generic_to_shared(Xs);
    const uint32_t ws_u = (uint32_t)__cvta_generic_to_shared(Ws);

    // ldmatrix addresses
    const uint32_t aX0 = xs_u + (uint32_t)((warpM + (l & 15)) * XRW + (l >> 4) * 4) * 4u;
    const uint32_t aX1 = aX0 + 16u * XRW * 4u;
    const uint32_t bW  = ws_u + (uint32_t)((warpN + (l & 7)) * XRW + ((l >> 3) & 1) * 4) * 4u;

    float acc[2][8][4];
#pragma unroll
    for (int m2 = 0; m2 < 2; m2++)
#pragma unroll
        for (int n = 0; n < 8; n++)
#pragma unroll
            for (int j = 0; j < 4; j++) acc[m2][n][j] = 0.f;

    const float* Xg = X + (size_t)(bm * 128) * DD;

    for (int k0 = 0; k0 < DD; k0 += 16) {
        __syncthreads();
        // ---- load X tile 128 x 16 (tf32)
#pragma unroll
        for (int it = 0; it < 2; it++) {
            const int idx = it * 256 + tid;
            const int r = idx >> 2, c4 = idx & 3;
            float4 v = *(const float4*)(Xg + (size_t)r * DD + k0 + c4 * 4);
            *(float4*)(Xs + r * XRW + c4 * 4) =
                make_float4(tf32r(v.x), tf32r(v.y), tf32r(v.z), tf32r(v.w));
        }
        // ---- load W tile transposed: Ws[n][k] = W[k0+k][bn*128+n], 4x4 blocks
        if (tid < 128) {
            const int kb = tid >> 5;        // 0..3 (k block of 4)
            const int nb = tid & 31;        // 0..31 (n block of 4)
            const float* src = W + (size_t)(k0 + kb * 4) * DD + bn * 128 + nb * 4;
            float4 x0 = *(const float4*)(src);
            float4 x1 = *(const float4*)(src + DD);
            float4 x2 = *(const float4*)(src + 2 * DD);
            float4 x3 = *(const float4*)(src + 3 * DD);
            float* dst = Ws + (nb * 4) * XRW + kb * 4;
            *(float4*)(dst + 0 * XRW) = make_float4(tf32r(x0.x), tf32r(x1.x), tf32r(x2.x), tf32r(x3.x));
            *(float4*)(dst + 1 * XRW) = make_float4(tf32r(x0.y), tf32r(x1.y), tf32r(x2.y), tf32r(x3.y));
            *(float4*)(dst + 2 * XRW) = make_float4(tf32r(x0.z), tf32r(x1.z), tf32r(x2.z), tf32r(x3.z));
            *(float4*)(dst + 3 * XRW) = make_float4(tf32r(x0.w), tf32r(x1.w), tf32r(x2.w), tf32r(x3.w));
        }
        __syncthreads();

        // ---- 2 k8 sub-steps
#pragma unroll
        for (int kk = 0; kk < 2; kk++) {
            const uint32_t koff = kk * 32u;    // 8 floats = 32 bytes
            uint32_t a0[4], a1[4];
            ldsm_x4(a0[0], a0[1], a0[2], a0[3], aX0 + koff);
            ldsm_x4(a1[0], a1[1], a1[2], a1[3], aX1 + koff);
#pragma unroll
            for (int n = 0; n < 8; n++) {
                uint32_t b0, b1;
                ldsm_x2(b0, b1, bW + (uint32_t)(n * 8 * XRW) * 4u + koff);
                mma_tf32(acc[0][n], a0[0], a0[1], a0[2], a0[3], b0, b1);
                mma_tf32(acc[1][n], a1[0], a1[1], a1[2], a1[3], b0, b1);
            }
        }
    }

    // ---- epilogue: add bias, store head-split [B,H,S,DH]
#pragma unroll
    for (int m2 = 0; m2 < 2; m2++) {
        const int m0 = bm * 128 + warpM + m2 * 16 + grp;
#pragma unroll
        for (int half = 0; half < 2; half++) {
            const int m = m0 + half * 8;
            const int b = m >> 11;
            const int s = m & 2047;
            float* orow = out + ((size_t)(b * HH) * SS + s) * DH;  // head 0 base
#pragma unroll
            for (int n = 0; n < 8; n++) {
                const int col = bn * 128 + warpN + n * 8 + 2 * tg;
                const int h = col >> 6;
                const int dh = col & 63;
                const float c0 = acc[m2][n][half * 2 + 0] + __ldg(&bias[col]);
                const float c1 = acc[m2][n][half * 2 + 1] + __ldg(&bias[col + 1]);
                *(float2*)(orow + (size_t)h * SS * DH + dh) = make_float2(c0, c1);
            }
        }
    }
}

// ---------------------------------------------------------------------------
// Kernel 2: flash attention on tensor cores (tf32 mma.sync) — unchanged R4.
// ---------------------------------------------------------------------------
#define RW 68

#define SMF (128*RW + 64*RW + 64*RW + 128*RW + 64)

__global__ __launch_bounds__(256, 2)
void attn_kernel(const float* __restrict__ mask, float* __restrict__ out)
{
    extern __shared__ float sm[];
    float* Qs  = sm;                 // [128][RW] Q (prescaled 0.125, tf32)
    float* Ks  = Qs + 128 * RW;      // [64][RW]  K rows [key][dh] (tf32)
    float* VTs = Ks + 64 * RW;       // [64][RW]  V transposed [dh][key] (tf32)
    float* Ps  = VTs + 64 * RW;      // [128][RW] P tile (tf32)
    float* Ms  = Ps + 128 * RW;      // [64] mask

    const int tid = threadIdx.x;
    const int w = tid >> 5;
    const int l = tid & 31;
    const int tg = l & 3;
    const int grp = l >> 2;

    const int bh = blockIdx.y;
    const int b = bh / HH;
    const int h = bh % HH;
    const int q0 = blockIdx.x * 128;

    const float* Qg = g_q + (size_t)bh * SS * DH;
    const float* Kg = g_k + (size_t)bh * SS * DH;
    const float* Vg = g_v + (size_t)bh * SS * DH;
    const float* mrow = mask + (size_t)b * SS;

    const uint32_t qs_u  = (uint32_t)__cvta_generic_to_shared(Qs);
    const uint32_t ks_u  = (uint32_t)__cvta_generic_to_shared(Ks);
    const uint32_t vts_u = (uint32_t)__cvta_generic_to_shared(VTs);
    const uint32_t ps_u  = (uint32_t)__cvta_generic_to_shared(Ps);

    const int aRow = w * 16 + (l & 15);
    const int aColX = (l >> 4) * 4;
    const uint32_t aQ = qs_u + (uint32_t)(aRow * RW + aColX) * 4u;
    const uint32_t aP = ps_u + (uint32_t)(aRow * RW + aColX) * 4u;
    const int bRow = (l & 7);
    const int bColX = ((l >> 3) & 1) * 4;
    const uint32_t bK = ks_u  + (uint32_t)(bRow * RW + bColX) * 4u;
    const uint32_t bV = vts_u + (uint32_t)(bRow * RW + bColX) * 4u;

    for (int i = tid; i < 128 * 16; i += 256) {
        const int r = i >> 4, c4 = i & 15;
        float4 v = *(const float4*)(Qg + (size_t)(q0 + r) * DH + c4 * 4);
        float4 o4 = make_float4(tf32r(v.x * 0.125f), tf32r(v.y * 0.125f),
                                tf32r(v.z * 0.125f), tf32r(v.w * 0.125f));
        *(float4*)(Qs + r * RW + c4 * 4) = o4;
    }

    float o[8][4];
#pragma unroll
    for (int n = 0; n < 8; n++)
#pragma unroll
        for (int j = 0; j < 4; j++) o[n][j] = 0.f;
    float mr0 = -1e30f, mr1 = -1e30f, lr0 = 0.f, lr1 = 0.f;

    for (int t = 0; t < SS / 64; t++) {
        const int k0 = t * 64;
        __syncthreads();

#pragma unroll
        for (int it = 0; it < 4; it++) {
            const int i = it * 256 + tid;
            const int r = i >> 4, c4 = i & 15;
            float4 v = *(const float4*)(Kg + (size_t)(k0 + r) * DH + c4 * 4);
            *(float4*)(Ks + r * RW + c4 * 4) =
                make_float4(tf32r(v.x), tf32r(v.y), tf32r(v.z), tf32r(v.w));
        }
        {
            const int db = tid & 15;
            const int kb = tid >> 4;
            const float* src = Vg + (size_t)(k0 + kb * 4) * DH + db * 4;
            float4 x0 = *(const float4*)(src);
            float4 x1 = *(const float4*)(src + DH);
            float4 x2 = *(const float4*)(src + 2 * DH);
            float4 x3 = *(const float4*)(src + 3 * DH);
            float* dst = VTs + (db * 4) * RW + kb * 4;
            *(float4*)(dst + 0 * RW) = make_float4(tf32r(x0.x), tf32r(x1.x), tf32r(x2.x), tf32r(x3.x));
            *(float4*)(dst + 1 * RW) = make_float4(tf32r(x0.y), tf32r(x1.y), tf32r(x2.y), tf32r(x3.y));
            *(float4*)(dst + 2 * RW) = make_float4(tf32r(x0.z), tf32r(x1.z), tf32r(x2.z), tf32r(x3.z));
            *(float4*)(dst + 3 * RW) = make_float4(tf32r(x0.w), tf32r(x1.w), tf32r(x2.w), tf32r(x3.w));
        }
        if (tid < 64) Ms[tid] = __ldg(mrow + k0 + tid);
        __syncthreads();

        float s[8][4];
#pragma unroll
        for (int n = 0; n < 8; n++)
#pragma unroll
            for (int j = 0; j < 4; j++) s[n][j] = 0.f;

#pragma unroll
        for (int kk = 0; kk < 8; kk++) {
            uint32_t a0, a1, a2, a3;
            ldsm_x4(a0, a1, a2, a3, aQ + kk * 32u);
#pragma unroll
            for (int n = 0; n < 8; n++) {
                uint32_t b0, b1;
                ldsm_x2(b0, b1, bK + (uint32_t)(n * 8 * RW) * 4u + kk * 32u);
                mma_tf32(s[n], a0, a1, a2, a3, b0, b1);
            }
        }

        float rx0 = -1e30f, rx1 = -1e30f;
#pragma unroll
        for (int n = 0; n < 8; n++) {
            const float mk0 = Ms[n * 8 + 2 * tg];
            const float mk1 = Ms[n * 8 + 2 * tg + 1];
            s[n][0] += mk0; s[n][1] += mk1;
            s[n][2] += mk0; s[n][3] += mk1;
            rx0 = fmaxf(rx0, fmaxf(s[n][0], s[n][1]));
            rx1 = fmaxf(rx1, fmaxf(s[n][2], s[n][3]));
        }
        rx0 = fmaxf(rx0, __shfl_xor_sync(0xffffffffu, rx0, 1));
        rx0 = fmaxf(rx0, __shfl_xor_sync(0xffffffffu, rx0, 2));
        rx1 = fmaxf(rx1, __shfl_xor_sync(0xffffffffu, rx1, 1));
        rx1 = fmaxf(rx1, __shfl_xor_sync(0xffffffffu, rx1, 2));

        const float mn0 = fmaxf(mr0, rx0);
        const float mn1 = fmaxf(mr1, rx1);
        const float c0 = __expf(mr0 - mn0);
        const float c1 = __expf(mr1 - mn1);

        const int row0 = w * 16 + grp;
        const int row1 = row0 + 8;
        float sum0 = 0.f, sum1 = 0.f;
#pragma unroll
        for (int n = 0; n < 8; n++) {
            const float p00 = __expf(s[n][0] - mn0);
            const float p01 = __expf(s[n][1] - mn0);
            const float p10 = __expf(s[n][2] - mn1);
            const float p11 = __expf(s[n][3] - mn1);
            sum0 += p00 + p01;
            sum1 += p10 + p11;
            *(float2*)(Ps + row0 * RW + n * 8 + 2 * tg) = make_float2(tf32r(p00), tf32r(p01));
            *(float2*)(Ps + row1 * RW + n * 8 + 2 * tg) = make_float2(tf32r(p10), tf32r(p11));
        }
        sum0 += __shfl_xor_sync(0xffffffffu, sum0, 1);
        sum0 += __shfl_xor_sync(0xffffffffu, sum0, 2);
        sum1 += __shfl_xor_sync(0xffffffffu, sum1, 1);
        sum1 += __shfl_xor_sync(0xffffffffu, sum1, 2);

        lr0 = lr0 * c0 + sum0;
        lr1 = lr1 * c1 + sum1;
        mr0 = mn0; mr1 = mn1;
#pragma unroll
        for (int n = 0; n < 8; n++) {
            o[n][0] *= c0; o[n][1] *= c0;
            o[n][2] *= c1; o[n][3] *= c1;
        }
        __syncwarp();

#pragma unroll
        for (int kk = 0; kk < 8; kk++) {
            uint32_t a0, a1, a2, a3;
            ldsm_x4(a0, a1, a2, a3, aP + kk * 32u);
#pragma unroll
            for (int n = 0; n < 8; n++) {
                uint32_t b0, b1;
                ldsm_x2(b0, b1, bV + (uint32_t)(n * 8 * RW) * 4u + kk * 32u);
                mma_tf32(o[n], a0, a1, a2, a3, b0, b1);
            }
        }
    }

    const float inv0 = 1.0f / lr0;
    const float inv1 = 1.0f / lr1;
    const int r0 = q0 + w * 16 + grp;
    const int r1 = r0 + 8;
#pragma unroll
    for (int n = 0; n < 8; n++) {
        const int col = h * DH + n * 8 + 2 * tg;
        *(float2*)(out + (size_t)(b * SS + r0) * DD + col) =
            make_float2(o[n][0] * inv0, o[n][1] * inv0);
        *(float2*)(out + (size_t)(b * SS + r1) * DD + col) =
            make_float2(o[n][2] * inv1, o[n][3] * inv1);
    }
}

// ---------------------------------------------------------------------------
extern "C" void kernel_launch(void* const* d_in, const int* in_sizes, int n_in,
                              void* d_out, int out_size)
{
    const float* hidden = (const float*)d_in[0];
    const float* mask   = (const float*)d_in[1];
    const float* Wq     = (const float*)d_in[2];
    const float* bq     = (const float*)d_in[3];
    const float* Wk     = (const float*)d_in[4];
    const float* bk     = (const float*)d_in[5];
    const float* Wv     = (const float*)d_in[6];
    const float* bv     = (const float*)d_in[7];
    float* out = (float*)d_out;

    const int smem_attn = SMF * sizeof(float);   // 104704 B
    cudaFuncSetAttribute(attn_kernel, cudaFuncAttributeMaxDynamicSharedMemorySize, smem_attn);

    qkv_kernel<<<dim3(64, 6, 3), 256>>>(hidden, Wq, bq, Wk, bk, Wv, bv);
    attn_kernel<<<dim3(SS / 128, BH), 256, smem_attn>>>(mask, out);
}

// round 6
// speedup vs baseline: 3.0806x; 1.0705x over previous
#include <cuda_runtime.h>
#include <cuda_bf16.h>
#include <cstdint>

// Problem constants
#define BB 4
#define SS 2048
#define DD 768
#define HH 12
#define DH 64
#define BH (BB*HH)          // 48

// Scratch: Q,K,V in [B,H,S,DH] layout
__device__ float g_q[BH * SS * DH];
__device__ float g_k[BH * SS * DH];
__device__ float g_v[BH * SS * DH];

// ---------------------------------------------------------------------------
// Tensor-core helpers (mma.sync m16n8k8 tf32 + ldmatrix)
// ---------------------------------------------------------------------------
__device__ __forceinline__ float tf32r(float x) {
    uint32_t u;
    asm("cvt.rna.tf32.f32 %0, %1;" : "=r"(u) : "f"(x));
    return __uint_as_float(u);
}
__device__ __forceinline__ void ldsm_x4(uint32_t& r0, uint32_t& r1, uint32_t& r2, uint32_t& r3, uint32_t a) {
    asm volatile("ldmatrix.sync.aligned.m8n8.x4.shared.b16 {%0,%1,%2,%3}, [%4];"
                 : "=r"(r0), "=r"(r1), "=r"(r2), "=r"(r3) : "r"(a));
}
__device__ __forceinline__ void ldsm_x2(uint32_t& r0, uint32_t& r1, uint32_t a) {
    asm volatile("ldmatrix.sync.aligned.m8n8.x2.shared.b16 {%0,%1}, [%2];"
                 : "=r"(r0), "=r"(r1) : "r"(a));
}
__device__ __forceinline__ void mma_tf32(float (&d)[4],
                                         uint32_t a0, uint32_t a1, uint32_t a2, uint32_t a3,
                                         uint32_t b0, uint32_t b1) {
    asm volatile("mma.sync.aligned.m16n8k8.row.col.f32.tf32.tf32.f32 "
                 "{%0,%1,%2,%3}, {%4,%5,%6,%7}, {%8,%9}, {%0,%1,%2,%3};"
                 : "+f"(d[0]), "+f"(d[1]), "+f"(d[2]), "+f"(d[3])
                 : "r"(a0), "r"(a1), "r"(a2), "r"(a3), "r"(b0), "r"(b1));
}

// ---------------------------------------------------------------------------
// Kernel 1: fused QKV projection on tensor cores (tf32 mma.sync) — unchanged.
// ---------------------------------------------------------------------------
#define XRW 20

__global__ __launch_bounds__(256, 2)
void qkv_kernel(const float* __restrict__ X,
                const float* __restrict__ Wq, const float* __restrict__ bq,
                const float* __restrict__ Wk, const float* __restrict__ bk,
                const float* __restrict__ Wv, const float* __restrict__ bv)
{
    __shared__ float Xs[128 * XRW];
    __shared__ float Ws[128 * XRW];

    const int z = blockIdx.z;
    const float* W    = (z == 0) ? Wq : (z == 1) ? Wk : Wv;
    const float* bias = (z == 0) ? bq : (z == 1) ? bk : bv;
    float* out        = (z == 0) ? g_q : (z == 1) ? g_k : g_v;

    const int bm = blockIdx.x;
    const int bn = blockIdx.y;
    const int tid = threadIdx.x;
    const int w = tid >> 5;
    const int l = tid & 31;
    const int tg = l & 3;
    const int grp = l >> 2;

    const int warpM = (w >> 1) * 32;
    const int warpN = (w & 1) * 64;

    const uint32_t xs_u = (uint32_t)__cvta_generic_to_shared(Xs);
    const uint32_t ws_u = (uint32_t)__cvta_generic_to_shared(Ws);

    const uint32_t aX0 = xs_u + (uint32_t)((warpM + (l & 15)) * XRW + (l >> 4) * 4) * 4u;
    const uint32_t aX1 = aX0 + 16u * XRW * 4u;
    const uint32_t bW  = ws_u + (uint32_t)((warpN + (l & 7)) * XRW + ((l >> 3) & 1) * 4) * 4u;

    float acc[2][8][4];
#pragma unroll
    for (int m2 = 0; m2 < 2; m2++)
#pragma unroll
        for (int n = 0; n < 8; n++)
#pragma unroll
            for (int j = 0; j < 4; j++) acc[m2][n][j] = 0.f;

    const float* Xg = X + (size_t)(bm * 128) * DD;

    for (int k0 = 0; k0 < DD; k0 += 16) {
        __syncthreads();
#pragma unroll
        for (int it = 0; it < 2; it++) {
            const int idx = it * 256 + tid;
            const int r = idx >> 2, c4 = idx & 3;
            float4 v = *(const float4*)(Xg + (size_t)r * DD + k0 + c4 * 4);
            *(float4*)(Xs + r * XRW + c4 * 4) =
                make_float4(tf32r(v.x), tf32r(v.y), tf32r(v.z), tf32r(v.w));
        }
        if (tid < 128) {
            const int kb = tid >> 5;
            const int nb = tid & 31;
            const float* src = W + (size_t)(k0 + kb * 4) * DD + bn * 128 + nb * 4;
            float4 x0 = *(const float4*)(src);
            float4 x1 = *(const float4*)(src + DD);
            float4 x2 = *(const float4*)(src + 2 * DD);
            float4 x3 = *(const float4*)(src + 3 * DD);
            float* dst = Ws + (nb * 4) * XRW + kb * 4;
            *(float4*)(dst + 0 * XRW) = make_float4(tf32r(x0.x), tf32r(x1.x), tf32r(x2.x), tf32r(x3.x));
            *(float4*)(dst + 1 * XRW) = make_float4(tf32r(x0.y), tf32r(x1.y), tf32r(x2.y), tf32r(x3.y));
            *(float4*)(dst + 2 * XRW) = make_float4(tf32r(x0.z), tf32r(x1.z), tf32r(x2.z), tf32r(x3.z));
            *(float4*)(dst + 3 * XRW) = make_float4(tf32r(x0.w), tf32r(x1.w), tf32r(x2.w), tf32r(x3.w));
        }
        __syncthreads();

#pragma unroll
        for (int kk = 0; kk < 2; kk++) {
            const uint32_t koff = kk * 32u;
            uint32_t a0[4], a1[4];
            ldsm_x4(a0[0], a0[1], a0[2], a0[3], aX0 + koff);
            ldsm_x4(a1[0], a1[1], a1[2], a1[3], aX1 + koff);
#pragma unroll
            for (int n = 0; n < 8; n++) {
                uint32_t b0, b1;
                ldsm_x2(b0, b1, bW + (uint32_t)(n * 8 * XRW) * 4u + koff);
                mma_tf32(acc[0][n], a0[0], a0[1], a0[2], a0[3], b0, b1);
                mma_tf32(acc[1][n], a1[0], a1[1], a1[2], a1[3], b0, b1);
            }
        }
    }

#pragma unroll
    for (int m2 = 0; m2 < 2; m2++) {
        const int m0 = bm * 128 + warpM + m2 * 16 + grp;
#pragma unroll
        for (int half = 0; half < 2; half++) {
            const int m = m0 + half * 8;
            const int b = m >> 11;
            const int s = m & 2047;
            float* orow = out + ((size_t)(b * HH) * SS + s) * DH;
#pragma unroll
            for (int n = 0; n < 8; n++) {
                const int col = bn * 128 + warpN + n * 8 + 2 * tg;
                const int h = col >> 6;
                const int dh = col & 63;
                const float c0 = acc[m2][n][half * 2 + 0] + __ldg(&bias[col]);
                const float c1 = acc[m2][n][half * 2 + 1] + __ldg(&bias[col + 1]);
                *(float2*)(orow + (size_t)h * SS * DH + dh) = make_float2(c0, c1);
            }
        }
    }
}

// ---------------------------------------------------------------------------
// Kernel 2: flash attention, tf32 mma.sync, m32 warp tile.
// 128 threads / 4 warps; warp w owns q rows [w*32, w*32+32) x all 64 keys.
// B-fragments (K^T, V^T) reused across 2 m16 tiles -> 1.5 wf/mma (was 2.5).
// grid = (S/128 = 16, B*H = 48), 2 CTAs/SM.
// ---------------------------------------------------------------------------
#define RW 68
#define SMF (128*RW + 64*RW + 64*RW + 128*RW + 64)

__global__ __launch_bounds__(128, 2)
void attn_kernel(const float* __restrict__ mask, float* __restrict__ out)
{
    extern __shared__ float sm[];
    float* Qs  = sm;                 // [128][RW]
    float* Ks  = Qs + 128 * RW;      // [64][RW]  [key][dh]
    float* VTs = Ks + 64 * RW;       // [64][RW]  [dh][key]
    float* Ps  = VTs + 64 * RW;      // [128][RW]
    float* Ms  = Ps + 128 * RW;      // [64]

    const int tid = threadIdx.x;
    const int w = tid >> 5;          // warp 0..3
    const int l = tid & 31;
    const int tg = l & 3;
    const int grp = l >> 2;

    const int bh = blockIdx.y;
    const int b = bh / HH;
    const int h = bh % HH;
    const int q0 = blockIdx.x * 128;

    const float* Qg = g_q + (size_t)bh * SS * DH;
    const float* Kg = g_k + (size_t)bh * SS * DH;
    const float* Vg = g_v + (size_t)bh * SS * DH;
    const float* mrow = mask + (size_t)b * SS;

    const uint32_t qs_u  = (uint32_t)__cvta_generic_to_shared(Qs);
    const uint32_t ks_u  = (uint32_t)__cvta_generic_to_shared(Ks);
    const uint32_t vts_u = (uint32_t)__cvta_generic_to_shared(VTs);
    const uint32_t ps_u  = (uint32_t)__cvta_generic_to_shared(Ps);

    // A-fragment addresses for the warp's two m16 tiles (rows w*32 / w*32+16)
    const uint32_t aQ0 = qs_u + (uint32_t)((w * 32 + (l & 15)) * RW + (l >> 4) * 4) * 4u;
    const uint32_t aQ1 = aQ0 + 16u * RW * 4u;
    const uint32_t aP0 = ps_u + (uint32_t)((w * 32 + (l & 15)) * RW + (l >> 4) * 4) * 4u;
    const uint32_t aP1 = aP0 + 16u * RW * 4u;
    // B-fragment addresses
    const uint32_t bK = ks_u  + (uint32_t)(((l & 7)) * RW + ((l >> 3) & 1) * 4) * 4u;
    const uint32_t bV = vts_u + (uint32_t)(((l & 7)) * RW + ((l >> 3) & 1) * 4) * 4u;

    // ---- load Q tile (prescale 0.125, tf32): 128 rows x 16 float4
#pragma unroll
    for (int it = 0; it < 16; it++) {
        const int i = it * 128 + tid;
        const int r = i >> 4, c4 = i & 15;
        float4 v = *(const float4*)(Qg + (size_t)(q0 + r) * DH + c4 * 4);
        *(float4*)(Qs + r * RW + c4 * 4) =
            make_float4(tf32r(v.x * 0.125f), tf32r(v.y * 0.125f),
                        tf32r(v.z * 0.125f), tf32r(v.w * 0.125f));
    }

    float o[2][8][4];
#pragma unroll
    for (int mt = 0; mt < 2; mt++)
#pragma unroll
        for (int n = 0; n < 8; n++)
#pragma unroll
            for (int j = 0; j < 4; j++) o[mt][n][j] = 0.f;
    float mr[4], lr[4];
#pragma unroll
    for (int i = 0; i < 4; i++) { mr[i] = -1e30f; lr[i] = 0.f; }

    for (int t = 0; t < SS / 64; t++) {
        const int k0 = t * 64;
        __syncthreads();

        // ---- load K tile [key][dh]: 64 x 16 float4
#pragma unroll
        for (int it = 0; it < 8; it++) {
            const int i = it * 128 + tid;
            const int r = i >> 4, c4 = i & 15;
            float4 v = *(const float4*)(Kg + (size_t)(k0 + r) * DH + c4 * 4);
            *(float4*)(Ks + r * RW + c4 * 4) =
                make_float4(tf32r(v.x), tf32r(v.y), tf32r(v.z), tf32r(v.w));
        }
        // ---- load V transposed [dh][key]: 256 4x4 blocks / 128 threads
#pragma unroll
        for (int it = 0; it < 2; it++) {
            const int idx = it * 128 + tid;
            const int db = idx & 15;
            const int kb = idx >> 4;
            const float* src = Vg + (size_t)(k0 + kb * 4) * DH + db * 4;
            float4 x0 = *(const float4*)(src);
            float4 x1 = *(const float4*)(src + DH);
            float4 x2 = *(const float4*)(src + 2 * DH);
            float4 x3 = *(const float4*)(src + 3 * DH);
            float* dst = VTs + (db * 4) * RW + kb * 4;
            *(float4*)(dst + 0 * RW) = make_float4(tf32r(x0.x), tf32r(x1.x), tf32r(x2.x), tf32r(x3.x));
            *(float4*)(dst + 1 * RW) = make_float4(tf32r(x0.y), tf32r(x1.y), tf32r(x2.y), tf32r(x3.y));
            *(float4*)(dst + 2 * RW) = make_float4(tf32r(x0.z), tf32r(x1.z), tf32r(x2.z), tf32r(x3.z));
            *(float4*)(dst + 3 * RW) = make_float4(tf32r(x0.w), tf32r(x1.w), tf32r(x2.w), tf32r(x3.w));
        }
        if (tid < 64) Ms[tid] = __ldg(mrow + k0 + tid);
        __syncthreads();

        // ---- QK: S(32x64) = Q(32xDH) * K^T, B reused across both m16 tiles
        float s[2][8][4];
#pragma unroll
        for (int mt = 0; mt < 2; mt++)
#pragma unroll
            for (int n = 0; n < 8; n++)
#pragma unroll
                for (int j = 0; j < 4; j++) s[mt][n][j] = 0.f;

#pragma unroll
        for (int kk = 0; kk < 8; kk++) {
            uint32_t a0[4], a1[4];
            ldsm_x4(a0[0], a0[1], a0[2], a0[3], aQ0 + kk * 32u);
            ldsm_x4(a1[0], a1[1], a1[2], a1[3], aQ1 + kk * 32u);
#pragma unroll
            for (int n = 0; n < 8; n++) {
                uint32_t b0, b1;
                ldsm_x2(b0, b1, bK + (uint32_t)(n * 8 * RW) * 4u + kk * 32u);
                mma_tf32(s[0][n], a0[0], a0[1], a0[2], a0[3], b0, b1);
                mma_tf32(s[1][n], a1[0], a1[1], a1[2], a1[3], b0, b1);
            }
        }

        // ---- mask + online softmax; lane owns 4 rows:
        //      mt0: grp, grp+8; mt1: grp+16, grp+24  (within warp's 32-row block)
        float rx[4] = {-1e30f, -1e30f, -1e30f, -1e30f};
#pragma unroll
        for (int mt = 0; mt < 2; mt++)
#pragma unroll
            for (int n = 0; n < 8; n++) {
                const float mk0 = Ms[n * 8 + 2 * tg];
                const float mk1 = Ms[n * 8 + 2 * tg + 1];
                s[mt][n][0] += mk0; s[mt][n][1] += mk1;
                s[mt][n][2] += mk0; s[mt][n][3] += mk1;
                rx[mt * 2 + 0] = fmaxf(rx[mt * 2 + 0], fmaxf(s[mt][n][0], s[mt][n][1]));
                rx[mt * 2 + 1] = fmaxf(rx[mt * 2 + 1], fmaxf(s[mt][n][2], s[mt][n][3]));
            }
#pragma unroll
        for (int i = 0; i < 4; i++) {
            rx[i] = fmaxf(rx[i], __shfl_xor_sync(0xffffffffu, rx[i], 1));
            rx[i] = fmaxf(rx[i], __shfl_xor_sync(0xffffffffu, rx[i], 2));
        }
        float mn[4], cc[4], sum[4];
#pragma unroll
        for (int i = 0; i < 4; i++) {
            mn[i] = fmaxf(mr[i], rx[i]);
            cc[i] = __expf(mr[i] - mn[i]);
            sum[i] = 0.f;
        }
        const int rowb = w * 32 + grp;
#pragma unroll
        for (int mt = 0; mt < 2; mt++) {
            const int r0 = rowb + mt * 16;
#pragma unroll
            for (int n = 0; n < 8; n++) {
                const float p00 = __expf(s[mt][n][0] - mn[mt * 2]);
                const float p01 = __expf(s[mt][n][1] - mn[mt * 2]);
                const float p10 = __expf(s[mt][n][2] - mn[mt * 2 + 1]);
                const float p11 = __expf(s[mt][n][3] - mn[mt * 2 + 1]);
                sum[mt * 2]     += p00 + p01;
                sum[mt * 2 + 1] += p10 + p11;
                *(float2*)(Ps + r0 * RW + n * 8 + 2 * tg)       = make_float2(tf32r(p00), tf32r(p01));
                *(float2*)(Ps + (r0 + 8) * RW + n * 8 + 2 * tg) = make_float2(tf32r(p10), tf32r(p11));
            }
        }
#pragma unroll
        for (int i = 0; i < 4; i++) {
            sum[i] += __shfl_xor_sync(0xffffffffu, sum[i], 1);
            sum[i] += __shfl_xor_sync(0xffffffffu, sum[i], 2);
            lr[i] = lr[i] * cc[i] + sum[i];
            mr[i] = mn[i];
        }
#pragma unroll
        for (int mt = 0; mt < 2; mt++)
#pragma unroll
            for (int n = 0; n < 8; n++) {
                o[mt][n][0] *= cc[mt * 2];     o[mt][n][1] *= cc[mt * 2];
                o[mt][n][2] *= cc[mt * 2 + 1]; o[mt][n][3] *= cc[mt * 2 + 1];
            }
        __syncwarp();   // Ps rows are warp-private

        // ---- PV: O(32x64) += P(32x64) * V, B reused across both m16 tiles
#pragma unroll
        for (int kk = 0; kk < 8; kk++) {
            uint32_t a0[4], a1[4];
            ldsm_x4(a0[0], a0[1], a0[2], a0[3], aP0 + kk * 32u);
            ldsm_x4(a1[0], a1[1], a1[2], a1[3], aP1 + kk * 32u);
#pragma unroll
            for (int n = 0; n < 8; n++) {
                uint32_t b0, b1;
                ldsm_x2(b0, b1, bV + (uint32_t)(n * 8 * RW) * 4u + kk * 32u);
                mma_tf32(o[0][n], a0[0], a0[1], a0[2], a0[3], b0, b1);
                mma_tf32(o[1][n], a1[0], a1[1], a1[2], a1[3], b0, b1);
            }
        }
    }

    // ---- epilogue: normalize, write ctx [B,S,D]
#pragma unroll
    for (int mt = 0; mt < 2; mt++) {
#pragma unroll
        for (int half = 0; half < 2; half++) {
            const int i = mt * 2 + half;
            const float inv = 1.0f / lr[i];
            const int r = q0 + w * 32 + mt * 16 + half * 8 + grp;
#pragma unroll
            for (int n = 0; n < 8; n++) {
                const int col = h * DH + n * 8 + 2 * tg;
                *(float2*)(out + (size_t)(b * SS + r) * DD + col) =
                    make_float2(o[mt][n][half * 2] * inv, o[mt][n][half * 2 + 1] * inv);
            }
        }
    }
}

// ---------------------------------------------------------------------------
extern "C" void kernel_launch(void* const* d_in, const int* in_sizes, int n_in,
                              void* d_out, int out_size)
{
    const float* hidden = (const float*)d_in[0];
    const float* mask   = (const float*)d_in[1];
    const float* Wq     = (const float*)d_in[2];
    const float* bq     = (const float*)d_in[3];
    const float* Wk     = (const float*)d_in[4];
    const float* bk     = (const float*)d_in[5];
    const float* Wv     = (const float*)d_in[6];
    const float* bv     = (const float*)d_in[7];
    float* out = (float*)d_out;

    const int smem_attn = SMF * sizeof(float);   // 104704 B
    cudaFuncSetAttribute(attn_kernel, cudaFuncAttributeMaxDynamicSharedMemorySize, smem_attn);

    qkv_kernel<<<dim3(64, 6, 3), 256>>>(hidden, Wq, bq, Wk, bk, Wv, bv);
    attn_kernel<<<dim3(SS / 128, BH), 128, smem_attn>>>(mask, out);
}

// round 7
// speedup vs baseline: 3.4526x; 1.1207x over previous
#include <cuda_runtime.h>
#include <cuda_bf16.h>
#include <cstdint>

// Problem constants
#define BB 4
#define SS 2048
#define DD 768
#define HH 12
#define DH 64
#define BH (BB*HH)          // 48

// Scratch: Q [bh][s][dh] (tf32, pre-scaled 0.125), K [bh][s][dh] (tf32),
//          V TRANSPOSED [bh][dh][s] (tf32)
__device__ float g_q[BH * SS * DH];
__device__ float g_k[BH * SS * DH];
__device__ float g_v[BH * SS * DH];

// ---------------------------------------------------------------------------
// Helpers
// ---------------------------------------------------------------------------
__device__ __forceinline__ float tf32r(float x) {
    uint32_t u;
    asm("cvt.rna.tf32.f32 %0, %1;" : "=r"(u) : "f"(x));
    return __uint_as_float(u);
}
__device__ __forceinline__ void ldsm_x4(uint32_t& r0, uint32_t& r1, uint32_t& r2, uint32_t& r3, uint32_t a) {
    asm volatile("ldmatrix.sync.aligned.m8n8.x4.shared.b16 {%0,%1,%2,%3}, [%4];"
                 : "=r"(r0), "=r"(r1), "=r"(r2), "=r"(r3) : "r"(a));
}
__device__ __forceinline__ void ldsm_x2(uint32_t& r0, uint32_t& r1, uint32_t a) {
    asm volatile("ldmatrix.sync.aligned.m8n8.x2.shared.b16 {%0,%1}, [%2];"
                 : "=r"(r0), "=r"(r1) : "r"(a));
}
__device__ __forceinline__ void mma_tf32(float (&d)[4],
                                         uint32_t a0, uint32_t a1, uint32_t a2, uint32_t a3,
                                         uint32_t b0, uint32_t b1) {
    asm volatile("mma.sync.aligned.m16n8k8.row.col.f32.tf32.tf32.f32 "
                 "{%0,%1,%2,%3}, {%4,%5,%6,%7}, {%8,%9}, {%0,%1,%2,%3};"
                 : "+f"(d[0]), "+f"(d[1]), "+f"(d[2]), "+f"(d[3])
                 : "r"(a0), "r"(a1), "r"(a2), "r"(a3), "r"(b0), "r"(b1));
}
__device__ __forceinline__ void cpa16(uint32_t dst, const float* src) {
    asm volatile("cp.async.cg.shared.global [%0], [%1], 16;" :: "r"(dst), "l"(src));
}
__device__ __forceinline__ void cpa_commit() {
    asm volatile("cp.async.commit_group;");
}
template <int N>
__device__ __forceinline__ void cpa_wait() {
    asm volatile("cp.async.wait_group %0;" :: "n"(N));
}

// ---------------------------------------------------------------------------
// Kernel 1: fused QKV projection, tf32 mma.sync. Epilogue stores tf32-rounded
// values (Q pre-scaled by 0.125; V transposed [bh][dh][s]).
// ---------------------------------------------------------------------------
#define XRW 20

__global__ __launch_bounds__(256, 2)
void qkv_kernel(const float* __restrict__ X,
                const float* __restrict__ Wq, const float* __restrict__ bq,
                const float* __restrict__ Wk, const float* __restrict__ bk,
                const float* __restrict__ Wv, const float* __restrict__ bv)
{
    __shared__ float Xs[128 * XRW];
    __shared__ float Ws[128 * XRW];

    const int z = blockIdx.z;
    const float* W    = (z == 0) ? Wq : (z == 1) ? Wk : Wv;
    const float* bias = (z == 0) ? bq : (z == 1) ? bk : bv;
    float* out        = (z == 0) ? g_q : (z == 1) ? g_k : g_v;

    const int bm = blockIdx.x;
    const int bn = blockIdx.y;
    const int tid = threadIdx.x;
    const int w = tid >> 5;
    const int l = tid & 31;
    const int tg = l & 3;
    const int grp = l >> 2;

    const int warpM = (w >> 1) * 32;
    const int warpN = (w & 1) * 64;

    const uint32_t xs_u = (uint32_t)__cvta_generic_to_shared(Xs);
    const uint32_t ws_u = (uint32_t)__cvta_generic_to_shared(Ws);

    const uint32_t aX0 = xs_u + (uint32_t)((warpM + (l & 15)) * XRW + (l >> 4) * 4) * 4u;
    const uint32_t aX1 = aX0 + 16u * XRW * 4u;
    const uint32_t bW  = ws_u + (uint32_t)((warpN + (l & 7)) * XRW + ((l >> 3) & 1) * 4) * 4u;

    float acc[2][8][4];
#pragma unroll
    for (int m2 = 0; m2 < 2; m2++)
#pragma unroll
        for (int n = 0; n < 8; n++)
#pragma unroll
            for (int j = 0; j < 4; j++) acc[m2][n][j] = 0.f;

    const float* Xg = X + (size_t)(bm * 128) * DD;

    for (int k0 = 0; k0 < DD; k0 += 16) {
        __syncthreads();
#pragma unroll
        for (int it = 0; it < 2; it++) {
            const int idx = it * 256 + tid;
            const int r = idx >> 2, c4 = idx & 3;
            float4 v = *(const float4*)(Xg + (size_t)r * DD + k0 + c4 * 4);
            *(float4*)(Xs + r * XRW + c4 * 4) =
                make_float4(tf32r(v.x), tf32r(v.y), tf32r(v.z), tf32r(v.w));
        }
        if (tid < 128) {
            const int kb = tid >> 5;
            const int nb = tid & 31;
            const float* src = W + (size_t)(k0 + kb * 4) * DD + bn * 128 + nb * 4;
            float4 x0 = *(const float4*)(src);
            float4 x1 = *(const float4*)(src + DD);
            float4 x2 = *(const float4*)(src + 2 * DD);
            float4 x3 = *(const float4*)(src + 3 * DD);
            float* dst = Ws + (nb * 4) * XRW + kb * 4;
            *(float4*)(dst + 0 * XRW) = make_float4(tf32r(x0.x), tf32r(x1.x), tf32r(x2.x), tf32r(x3.x));
            *(float4*)(dst + 1 * XRW) = make_float4(tf32r(x0.y), tf32r(x1.y), tf32r(x2.y), tf32r(x3.y));
            *(float4*)(dst + 2 * XRW) = make_float4(tf32r(x0.z), tf32r(x1.z), tf32r(x2.z), tf32r(x3.z));
            *(float4*)(dst + 3 * XRW) = make_float4(tf32r(x0.w), tf32r(x1.w), tf32r(x2.w), tf32r(x3.w));
        }
        __syncthreads();

#pragma unroll
        for (int kk = 0; kk < 2; kk++) {
            const uint32_t koff = kk * 32u;
            uint32_t a0[4], a1[4];
            ldsm_x4(a0[0], a0[1], a0[2], a0[3], aX0 + koff);
            ldsm_x4(a1[0], a1[1], a1[2], a1[3], aX1 + koff);
#pragma unroll
            for (int n = 0; n < 8; n++) {
                uint32_t b0, b1;
                ldsm_x2(b0, b1, bW + (uint32_t)(n * 8 * XRW) * 4u + koff);
                mma_tf32(acc[0][n], a0[0], a0[1], a0[2], a0[3], b0, b1);
                mma_tf32(acc[1][n], a1[0], a1[1], a1[2], a1[3], b0, b1);
            }
        }
    }

    // epilogue: add bias, round to tf32, store (Q scaled; V transposed)
#pragma unroll
    for (int m2 = 0; m2 < 2; m2++) {
        const int m0 = bm * 128 + warpM + m2 * 16 + grp;
#pragma unroll
        for (int half = 0; half < 2; half++) {
            const int m = m0 + half * 8;
            const int b = m >> 11;
            const int s = m & 2047;
#pragma unroll
            for (int n = 0; n < 8; n++) {
                const int col = bn * 128 + warpN + n * 8 + 2 * tg;
                const int h = col >> 6;
                const int dh = col & 63;
                float c0 = acc[m2][n][half * 2 + 0] + __ldg(&bias[col]);
                float c1 = acc[m2][n][half * 2 + 1] + __ldg(&bias[col + 1]);
                if (z == 0) {
                    c0 = tf32r(c0 * 0.125f); c1 = tf32r(c1 * 0.125f);
                    *(float2*)(out + ((size_t)(b * HH + h) * SS + s) * DH + dh) =
                        make_float2(c0, c1);
                } else if (z == 1) {
                    *(float2*)(out + ((size_t)(b * HH + h) * SS + s) * DH + dh) =
                        make_float2(tf32r(c0), tf32r(c1));
                } else {
                    float* vb = out + ((size_t)(b * HH + h) * DH + dh) * SS + s;
                    vb[0]  = tf32r(c0);
                    vb[SS] = tf32r(c1);
                }
            }
        }
    }
}

// ---------------------------------------------------------------------------
// Kernel 2: flash attention, tf32 mma.sync, m32 warp tile, cp.async
// double-buffered K/V. 128 threads / 4 warps. grid = (16, 48), 2 CTAs/SM.
// ---------------------------------------------------------------------------
#define RW 68
#define K_OFF(buf) ((buf) * 64 * RW)
#define V_OFF(buf) ((2 + (buf)) * 64 * RW)
#define PS_OFF     (4 * 64 * RW)
#define MS_OFF     (PS_OFF + 128 * RW)
#define SMF        (MS_OFF + SS)          // 28160 floats = 112640 B

__global__ __launch_bounds__(128, 2)
void attn_kernel(const float* __restrict__ mask, float* __restrict__ out)
{
    extern __shared__ float sm[];
    float* Ps = sm + PS_OFF;
    float* Ms = sm + MS_OFF;

    const int tid = threadIdx.x;
    const int w = tid >> 5;
    const int l = tid & 31;
    const int tg = l & 3;
    const int grp = l >> 2;

    const int bh = blockIdx.y;
    const int b = bh / HH;
    const int h = bh % HH;
    const int q0 = blockIdx.x * 128;

    const float* Qg  = g_q + (size_t)bh * SS * DH;
    const float* Kg  = g_k + (size_t)bh * SS * DH;
    const float* VgT = g_v + (size_t)bh * SS * DH;   // [dh][s]
    const float* mrow = mask + (size_t)b * SS;

    const uint32_t sm_u = (uint32_t)__cvta_generic_to_shared(sm);
    const uint32_t ps_u = sm_u + PS_OFF * 4u;

    // ldmatrix lane addresses
    const uint32_t aP0 = ps_u + (uint32_t)((w * 32 + (l & 15)) * RW + (l >> 4) * 4) * 4u;
    const uint32_t aP1 = aP0 + 16u * RW * 4u;
    const uint32_t bLane = (uint32_t)(((l & 7)) * RW + ((l >> 3) & 1) * 4) * 4u;

    // ---- prologue: issue tile 0 (K,V) + mask row as cp.async group 0
    {
#pragma unroll
        for (int it = 0; it < 8; it++) {
            const int idx = it * 128 + tid;
            const int r = idx >> 4, c = idx & 15;
            cpa16(sm_u + (uint32_t)(K_OFF(0) + r * RW + c * 4) * 4u,
                  Kg + (size_t)r * DH + c * 4);
        }
#pragma unroll
        for (int it = 0; it < 8; it++) {
            const int idx = it * 128 + tid;
            const int d = idx >> 4, c = idx & 15;
            cpa16(sm_u + (uint32_t)(V_OFF(0) + d * RW + c * 4) * 4u,
                  VgT + (size_t)d * SS + c * 4);
        }
#pragma unroll
        for (int it = 0; it < 4; it++) {
            const int c = it * 128 + tid;      // float4 index 0..511
            cpa16(sm_u + (uint32_t)(MS_OFF + c * 4) * 4u, mrow + c * 4);
        }
        cpa_commit();
    }

    // ---- stage Q tile into Ps, load Q fragments to registers
#pragma unroll
    for (int it = 0; it < 16; it++) {
        const int i = it * 128 + tid;
        const int r = i >> 4, c4 = i & 15;
        *(float4*)(Ps + r * RW + c4 * 4) =
            *(const float4*)(Qg + (size_t)(q0 + r) * DH + c4 * 4);
    }
    __syncthreads();

    uint32_t qf[2][8][4];
    {
        const uint32_t aQ0 = ps_u + (uint32_t)((w * 32 + (l & 15)) * RW + (l >> 4) * 4) * 4u;
#pragma unroll
        for (int mt = 0; mt < 2; mt++)
#pragma unroll
            for (int kk = 0; kk < 8; kk++)
                ldsm_x4(qf[mt][kk][0], qf[mt][kk][1], qf[mt][kk][2], qf[mt][kk][3],
                        aQ0 + (uint32_t)(mt * 16 * RW) * 4u + kk * 32u);
    }

    float o[2][8][4];
#pragma unroll
    for (int mt = 0; mt < 2; mt++)
#pragma unroll
        for (int n = 0; n < 8; n++)
#pragma unroll
            for (int j = 0; j < 4; j++) o[mt][n][j] = 0.f;
    float mr[4], lr[4];
#pragma unroll
    for (int i = 0; i < 4; i++) { mr[i] = -1e30f; lr[i] = 0.f; }

    const int NT = SS / 64;   // 32
    for (int t = 0; t < NT; t++) {
        const int buf = t & 1;
        const uint32_t kBase = sm_u + (uint32_t)K_OFF(buf) * 4u + bLane;
        const uint32_t vBase = sm_u + (uint32_t)V_OFF(buf) * 4u + bLane;

        // issue next tile into the other buffer, then drain current
        if (t + 1 < NT) {
            const int nb = 1 - buf;
            const int nk0 = (t + 1) * 64;
#pragma unroll
            for (int it = 0; it < 8; it++) {
                const int idx = it * 128 + tid;
                const int r = idx >> 4, c = idx & 15;
                cpa16(sm_u + (uint32_t)(K_OFF(nb) + r * RW + c * 4) * 4u,
                      Kg + (size_t)(nk0 + r) * DH + c * 4);
            }
#pragma unroll
            for (int it = 0; it < 8; it++) {
                const int idx = it * 128 + tid;
                const int d = idx >> 4, c = idx & 15;
                cpa16(sm_u + (uint32_t)(V_OFF(nb) + d * RW + c * 4) * 4u,
                      VgT + (size_t)d * SS + nk0 + c * 4);
            }
            cpa_commit();
            cpa_wait<1>();
        } else {
            cpa_wait<0>();
        }
        __syncthreads();   // current buffer visible to all warps

        // ---- QK: S(32x64), Q frags from registers, K B-frags from smem
        float s[2][8][4];
#pragma unroll
        for (int mt = 0; mt < 2; mt++)
#pragma unroll
            for (int n = 0; n < 8; n++)
#pragma unroll
                for (int j = 0; j < 4; j++) s[mt][n][j] = 0.f;

#pragma unroll
        for (int kk = 0; kk < 8; kk++) {
#pragma unroll
            for (int n = 0; n < 8; n++) {
                uint32_t b0, b1;
                ldsm_x2(b0, b1, kBase + (uint32_t)(n * 8 * RW) * 4u + kk * 32u);
                mma_tf32(s[0][n], qf[0][kk][0], qf[0][kk][1], qf[0][kk][2], qf[0][kk][3], b0, b1);
                mma_tf32(s[1][n], qf[1][kk][0], qf[1][kk][1], qf[1][kk][2], qf[1][kk][3], b0, b1);
            }
        }

        // ---- mask + online softmax (lane owns 4 rows)
        const int k0 = t * 64;
        float rx[4] = {-1e30f, -1e30f, -1e30f, -1e30f};
#pragma unroll
        for (int mt = 0; mt < 2; mt++)
#pragma unroll
            for (int n = 0; n < 8; n++) {
                const float mk0 = Ms[k0 + n * 8 + 2 * tg];
                const float mk1 = Ms[k0 + n * 8 + 2 * tg + 1];
                s[mt][n][0] += mk0; s[mt][n][1] += mk1;
                s[mt][n][2] += mk0; s[mt][n][3] += mk1;
                rx[mt * 2 + 0] = fmaxf(rx[mt * 2 + 0], fmaxf(s[mt][n][0], s[mt][n][1]));
                rx[mt * 2 + 1] = fmaxf(rx[mt * 2 + 1], fmaxf(s[mt][n][2], s[mt][n][3]));
            }
#pragma unroll
        for (int i = 0; i < 4; i++) {
            rx[i] = fmaxf(rx[i], __shfl_xor_sync(0xffffffffu, rx[i], 1));
            rx[i] = fmaxf(rx[i], __shfl_xor_sync(0xffffffffu, rx[i], 2));
        }
        float mn[4], cc[4], sum[4];
#pragma unroll
        for (int i = 0; i < 4; i++) {
            mn[i] = fmaxf(mr[i], rx[i]);
            cc[i] = __expf(mr[i] - mn[i]);
            sum[i] = 0.f;
        }
        const int rowb = w * 32 + grp;
#pragma unroll
        for (int mt = 0; mt < 2; mt++) {
            const int r0 = rowb + mt * 16;
#pragma unroll
            for (int n = 0; n < 8; n++) {
                const float p00 = __expf(s[mt][n][0] - mn[mt * 2]);
                const float p01 = __expf(s[mt][n][1] - mn[mt * 2]);
                const float p10 = __expf(s[mt][n][2] - mn[mt * 2 + 1]);
                const float p11 = __expf(s[mt][n][3] - mn[mt * 2 + 1]);
                sum[mt * 2]     += p00 + p01;
                sum[mt * 2 + 1] += p10 + p11;
                *(float2*)(Ps + r0 * RW + n * 8 + 2 * tg)       = make_float2(tf32r(p00), tf32r(p01));
                *(float2*)(Ps + (r0 + 8) * RW + n * 8 + 2 * tg) = make_float2(tf32r(p10), tf32r(p11));
            }
        }
#pragma unroll
        for (int i = 0; i < 4; i++) {
            sum[i] += __shfl_xor_sync(0xffffffffu, sum[i], 1);
            sum[i] += __shfl_xor_sync(0xffffffffu, sum[i], 2);
            lr[i] = lr[i] * cc[i] + sum[i];
            mr[i] = mn[i];
        }
#pragma unroll
        for (int mt = 0; mt < 2; mt++)
#pragma unroll
            for (int n = 0; n < 8; n++) {
                o[mt][n][0] *= cc[mt * 2];     o[mt][n][1] *= cc[mt * 2];
                o[mt][n][2] *= cc[mt * 2 + 1]; o[mt][n][3] *= cc[mt * 2 + 1];
            }
        __syncwarp();   // Ps rows are warp-private

        // ---- PV: O(32x64) += P * V
#pragma unroll
        for (int kk = 0; kk < 8; kk++) {
            uint32_t a0[4], a1[4];
            ldsm_x4(a0[0], a0[1], a0[2], a0[3], aP0 + kk * 32u);
            ldsm_x4(a1[0], a1[1], a1[2], a1[3], aP1 + kk * 32u);
#pragma unroll
            for (int n = 0; n < 8; n++) {
                uint32_t b0, b1;
                ldsm_x2(b0, b1, vBase + (uint32_t)(n * 8 * RW) * 4u + kk * 32u);
                mma_tf32(o[0][n], a0[0], a0[1], a0[2], a0[3], b0, b1);
                mma_tf32(o[1][n], a1[0], a1[1], a1[2], a1[3], b0, b1);
            }
        }
        __syncthreads();   // all reads of buf done before t+2 overwrites it
    }

    // ---- epilogue
#pragma unroll
    for (int mt = 0; mt < 2; mt++) {
#pragma unroll
        for (int half = 0; half < 2; half++) {
            const int i = mt * 2 + half;
            const float inv = 1.0f / lr[i];
            const int r = q0 + w * 32 + mt * 16 + half * 8 + grp;
#pragma unroll
            for (int n = 0; n < 8; n++) {
                const int col = h * DH + n * 8 + 2 * tg;
                *(float2*)(out + (size_t)(b * SS + r) * DD + col) =
                    make_float2(o[mt][n][half * 2] * inv, o[mt][n][half * 2 + 1] * inv);
            }
        }
    }
}

// ---------------------------------------------------------------------------
extern "C" void kernel_launch(void* const* d_in, const int* in_sizes, int n_in,
                              void* d_out, int out_size)
{
    const float* hidden = (const float*)d_in[0];
    const float* mask   = (const float*)d_in[1];
    const float* Wq     = (const float*)d_in[2];
    const float* bq     = (const float*)d_in[3];
    const float* Wk     = (const float*)d_in[4];
    const float* bk     = (const float*)d_in[5];
    const float* Wv     = (const float*)d_in[6];
    const float* bv     = (const float*)d_in[7];
    float* out = (float*)d_out;

    const int smem_attn = SMF * sizeof(float);   // 112640 B
    cudaFuncSetAttribute(attn_kernel, cudaFuncAttributeMaxDynamicSharedMemorySize, smem_attn);

    qkv_kernel<<<dim3(64, 6, 3), 256>>>(hidden, Wq, bq, Wk, bk, Wv, bv);
    attn_kernel<<<dim3(SS / 128, BH), 128, smem_attn>>>(mask, out);
}